// round 2
// baseline (speedup 1.0000x reference)
#include <cuda_runtime.h>
#include <cuda_bf16.h>
#include <math.h>

// Problem constants
#define NN 50000
#define EE 800000
#define ETOT (EE + NN)   // 850000 (edges + self loops)
#define FF 128
#define DD 64
#define GG 32
#define CC 3

// ---------------- device scratch (static; no allocation allowed) ----------------
__device__ float g_bufA[(size_t)NN * 256];
__device__ float g_bufB[(size_t)NN * 256];
__device__ float g_als[NN * 4];
__device__ float g_ald[NN * 4];
__device__ int   g_rowptr[NN + 1];
__device__ int   g_cursor[NN];         // counts, then running cursor
__device__ int   g_esrc[ETOT];
__device__ int   g_eid[ETOT];
__device__ float g_pool[GG * DD];
__device__ float g_cnt[GG];
__device__ int   g_is64_ei;
__device__ int   g_is64_b;

// ---------------- helpers ----------------
__device__ __forceinline__ float lrelu(float x) { return x > 0.f ? x : 0.2f * x; }

__device__ __forceinline__ int ld_idx(const void* p, long long i, int is64) {
    if (is64) return ((const int*)p)[2 * i];   // little-endian low word
    return ((const int*)p)[i];
}

// tf32 split: x = hi + lo (both tf32-representable)
__device__ __forceinline__ float2 split_tf32(float x) {
    unsigned hi;
    asm("cvt.rna.tf32.f32 %0, %1;" : "=r"(hi) : "f"(x));
    float hif = __uint_as_float(hi);
    float r = x - hif;
    unsigned lo;
    asm("cvt.rna.tf32.f32 %0, %1;" : "=r"(lo) : "f"(r));
    return make_float2(__uint_as_float(hi), __uint_as_float(lo));
}

__device__ __forceinline__ void mma_tf32(float4& d,
                                         unsigned a0, unsigned a1, unsigned a2, unsigned a3,
                                         unsigned b0, unsigned b1) {
    asm volatile(
        "mma.sync.aligned.m16n8k8.row.col.f32.tf32.tf32.f32 "
        "{%0,%1,%2,%3},{%4,%5,%6,%7},{%8,%9},{%0,%1,%2,%3};"
        : "+f"(d.x), "+f"(d.y), "+f"(d.z), "+f"(d.w)
        : "r"(a0), "r"(a1), "r"(a2), "r"(a3), "r"(b0), "r"(b1));
}

// swizzled smem index: float2 array, row stride 17, 16 cols used
#define SWIDX(m, k) ((m) * 17 + (((k) + (((m) & 3) << 2)) & 15))

// ---------------- zero scratch + dtype detection ----------------
__global__ void zero_k(const void* ei, const void* batch) {
    int i = blockIdx.x * blockDim.x + threadIdx.x;
    if (i < NN) g_cursor[i] = 0;
    if (i < GG * DD) g_pool[i] = 0.f;
    if (i < GG) g_cnt[i] = 0.f;
    if (i == 0) {
        const int* p = (const int*)ei;
        bool z = true;
        #pragma unroll
        for (int j = 0; j < 16; j++) z = z && (p[2 * j + 1] == 0);
        g_is64_ei = z ? 1 : 0;
        const int* q = (const int*)batch;
        bool zb = true;
        #pragma unroll
        for (int j = 0; j < 16; j++) zb = zb && (q[NN - 1 - 2 * j] == 0);
        g_is64_b = zb ? 1 : 0;
    }
}

// ---------------- CSR build ----------------
__global__ void count_k(const void* ei) {
    long long e = (long long)blockIdx.x * blockDim.x + threadIdx.x;
    if (e >= ETOT) return;
    int is64 = g_is64_ei;
    int d = (e < EE) ? ld_idx(ei, (long long)EE + e, is64) : (int)(e - EE);
    atomicAdd(&g_cursor[d], 1);
}

// parallel chunked scan: 1 block, 1024 threads, each owns 49 contiguous elems
__global__ void scan_k() {
    __shared__ int wsum[32];
    const int CH = 49;  // 1024*49 = 50176 >= NN
    int t = threadIdx.x;
    int base = t * CH;
    int s = 0;
    for (int i = 0; i < CH; i++) {
        int idx = base + i;
        if (idx < NN) s += g_cursor[idx];
    }
    int lane = t & 31, w = t >> 5;
    int v = s;
    #pragma unroll
    for (int o = 1; o < 32; o <<= 1) {
        int u = __shfl_up_sync(0xffffffffu, v, o);
        if (lane >= o) v += u;
    }
    if (lane == 31) wsum[w] = v;
    __syncthreads();
    if (w == 0) {
        int x = wsum[lane];
        #pragma unroll
        for (int o = 1; o < 32; o <<= 1) {
            int u = __shfl_up_sync(0xffffffffu, x, o);
            if (lane >= o) x += u;
        }
        wsum[lane] = x;
    }
    __syncthreads();
    int excl = v - s + (w > 0 ? wsum[w - 1] : 0);
    for (int i = 0; i < CH; i++) {
        int idx = base + i;
        if (idx < NN) {
            int c = g_cursor[idx];
            g_rowptr[idx] = excl;
            g_cursor[idx] = excl;
            excl += c;
        }
    }
    if (t == 1023) g_rowptr[NN] = excl;
}

__global__ void scatter_k(const void* ei) {
    long long e = (long long)blockIdx.x * blockDim.x + threadIdx.x;
    if (e >= ETOT) return;
    int is64 = g_is64_ei;
    int s, d;
    if (e < EE) {
        s = ld_idx(ei, e, is64);
        d = ld_idx(ei, (long long)EE + e, is64);
    } else {
        s = d = (int)(e - EE);
    }
    int pos = atomicAdd(&g_cursor[d], 1);
    g_esrc[pos] = s;
    g_eid[pos]  = (int)e;
}

// ---------------- 3xTF32 tensor-core GEMM: C[M,Nc] = A[M,K] @ B[K,Nc] ----------------
// Block tile 128x128, 8 warps (2M x 4N grid of 64x32 warp tiles), BK=16.
// fp32 accuracy via hi/lo tf32 split (3 MMAs per k-step).
__global__ void __launch_bounds__(256) gemm_tf32_k(const float* __restrict__ A,
                                                   const float* __restrict__ B,
                                                   float* __restrict__ Cm,
                                                   int M, int K, int Nc) {
    __shared__ float2 As[128 * 17];
    __shared__ float2 Bs[128 * 17];

    int tid = threadIdx.x;
    int rowBase = blockIdx.y * 128;
    int colBase = blockIdx.x * 128;
    int warp = tid >> 5, lane = tid & 31;
    int gid = lane >> 2, tig = lane & 3;
    int mw = (warp & 1) * 64;   // warp M offset
    int nw = (warp >> 1) * 32;  // warp N offset

    float4 acc[4][4];
    #pragma unroll
    for (int i = 0; i < 4; i++)
        #pragma unroll
        for (int j = 0; j < 4; j++) acc[i][j] = make_float4(0.f, 0.f, 0.f, 0.f);

    float pa[2][4];
    float pb[2][4];

    // --- global load into regs (prefetch) ---
    auto loadA = [&](int kt) {
        #pragma unroll
        for (int j = 0; j < 2; j++) {
            int s = tid + 256 * j;
            int m = s >> 2, kq = (s & 3) << 2;
            if (rowBase + m < M) {
                float4 v = *(const float4*)(A + (size_t)(rowBase + m) * K + kt + kq);
                pa[j][0] = v.x; pa[j][1] = v.y; pa[j][2] = v.z; pa[j][3] = v.w;
            } else {
                pa[j][0] = pa[j][1] = pa[j][2] = pa[j][3] = 0.f;
            }
        }
    };
    auto loadB = [&](int kt) {
        #pragma unroll
        for (int j = 0; j < 2; j++) {
            int s = tid + 256 * j;
            int n = s & 127, kq = (s >> 7) << 2;
            #pragma unroll
            for (int i = 0; i < 4; i++) {
                float v = 0.f;
                if (colBase + n < Nc) v = B[(size_t)(kt + kq + i) * Nc + colBase + n];
                pb[j][i] = v;
            }
        }
    };
    // --- split + store to swizzled smem ---
    auto storeS = [&]() {
        #pragma unroll
        for (int j = 0; j < 2; j++) {
            int s = tid + 256 * j;
            int m = s >> 2, kq = (s & 3) << 2;
            #pragma unroll
            for (int i = 0; i < 4; i++) As[SWIDX(m, kq + i)] = split_tf32(pa[j][i]);
        }
        #pragma unroll
        for (int j = 0; j < 2; j++) {
            int s = tid + 256 * j;
            int n = s & 127, kq = (s >> 7) << 2;
            #pragma unroll
            for (int i = 0; i < 4; i++) Bs[SWIDX(n, kq + i)] = split_tf32(pb[j][i]);
        }
    };
    // --- mma over current smem chunk ---
    auto compute = [&]() {
        #pragma unroll
        for (int ks = 0; ks < 2; ks++) {
            int k0 = ks * 8;
            unsigned ah[4][4], alo[4][4];
            #pragma unroll
            for (int mt = 0; mt < 4; mt++) {
                int r0 = mw + mt * 16 + gid;
                float2 v0 = As[SWIDX(r0, k0 + tig)];
                float2 v1 = As[SWIDX(r0 + 8, k0 + tig)];
                float2 v2 = As[SWIDX(r0, k0 + tig + 4)];
                float2 v3 = As[SWIDX(r0 + 8, k0 + tig + 4)];
                ah[mt][0] = __float_as_uint(v0.x); alo[mt][0] = __float_as_uint(v0.y);
                ah[mt][1] = __float_as_uint(v1.x); alo[mt][1] = __float_as_uint(v1.y);
                ah[mt][2] = __float_as_uint(v2.x); alo[mt][2] = __float_as_uint(v2.y);
                ah[mt][3] = __float_as_uint(v3.x); alo[mt][3] = __float_as_uint(v3.y);
            }
            unsigned bh[4][2], bl[4][2];
            #pragma unroll
            for (int nt = 0; nt < 4; nt++) {
                int n = nw + nt * 8 + gid;
                float2 w0 = Bs[SWIDX(n, k0 + tig)];
                float2 w1 = Bs[SWIDX(n, k0 + tig + 4)];
                bh[nt][0] = __float_as_uint(w0.x); bl[nt][0] = __float_as_uint(w0.y);
                bh[nt][1] = __float_as_uint(w1.x); bl[nt][1] = __float_as_uint(w1.y);
            }
            #pragma unroll
            for (int mt = 0; mt < 4; mt++)
                #pragma unroll
                for (int nt = 0; nt < 4; nt++) {
                    mma_tf32(acc[mt][nt], ah[mt][0], ah[mt][1], ah[mt][2], ah[mt][3],
                             bh[nt][0], bh[nt][1]);
                    mma_tf32(acc[mt][nt], ah[mt][0], ah[mt][1], ah[mt][2], ah[mt][3],
                             bl[nt][0], bl[nt][1]);
                    mma_tf32(acc[mt][nt], alo[mt][0], alo[mt][1], alo[mt][2], alo[mt][3],
                             bh[nt][0], bh[nt][1]);
                }
        }
    };

    loadA(0);
    loadB(0);
    storeS();
    __syncthreads();
    for (int kt = 16;; kt += 16) {
        bool more = kt < K;
        if (more) { loadA(kt); loadB(kt); }
        compute();
        if (!more) break;
        __syncthreads();
        storeS();
        __syncthreads();
    }

    #pragma unroll
    for (int mt = 0; mt < 4; mt++) {
        int r0 = rowBase + mw + mt * 16 + gid;
        #pragma unroll
        for (int nt = 0; nt < 4; nt++) {
            int c = colBase + nw + nt * 8 + 2 * tig;
            if (c < Nc) {
                if (r0 < M)
                    *(float2*)(Cm + (size_t)r0 * Nc + c) =
                        make_float2(acc[mt][nt].x, acc[mt][nt].y);
                if (r0 + 8 < M)
                    *(float2*)(Cm + (size_t)(r0 + 8) * Nc + c) =
                        make_float2(acc[mt][nt].z, acc[mt][nt].w);
            }
        }
    }
}

// ---------------- per-node attention logits al_s, al_d ----------------
template <int HEADS>
__global__ void __launch_bounds__(256) compute_al_k(const float* __restrict__ h,
                                                    const float* __restrict__ a_s,
                                                    const float* __restrict__ a_d) {
    constexpr int HD = HEADS * DD;
    constexpr int LPH = 32 / HEADS;       // lanes per head
    constexpr int CPL = DD / LPH;         // cols per lane
    int wid = (blockIdx.x * blockDim.x + threadIdx.x) >> 5;
    int lane = threadIdx.x & 31;
    if (wid >= NN) return;
    int hh = lane / LPH;
    int j = lane % LPH;
    const float* row = h + (size_t)wid * HD + hh * DD + j * CPL;
    const float* asr = a_s + hh * DD + j * CPL;
    const float* adr = a_d + hh * DD + j * CPL;
    float ss = 0.f, sd = 0.f;
    #pragma unroll
    for (int c = 0; c < CPL; c++) {
        float v = row[c];
        ss += v * asr[c];
        sd += v * adr[c];
    }
    #pragma unroll
    for (int off = LPH / 2; off; off >>= 1) {
        ss += __shfl_down_sync(0xffffffffu, ss, off);
        sd += __shfl_down_sync(0xffffffffu, sd, off);
    }
    if (j == 0) {
        g_als[wid * HEADS + hh] = ss;
        g_ald[wid * HEADS + hh] = sd;
    }
}

// ---------------- GAT aggregation (warp per dst) ----------------
template <int HEADS, bool DOELU>
__global__ void __launch_bounds__(256) aggregate_k(const float* __restrict__ hlin,
                                                   const float* __restrict__ bias,
                                                   float* __restrict__ hout,
                                                   float* __restrict__ att) {
    int wid = (blockIdx.x * blockDim.x + threadIdx.x) >> 5;
    int lane = threadIdx.x & 31;
    if (wid >= NN) return;
    int n = wid;
    int st = g_rowptr[n], en = g_rowptr[n + 1];

    float ald[HEADS];
    if (HEADS == 4) {
        float4 v = ((const float4*)g_ald)[n];
        ald[0] = v.x; ald[1] = v.y; ald[2] = v.z; ald[3] = v.w;
    } else {
        ald[0] = g_ald[n];
    }

    float m[HEADS];
    #pragma unroll
    for (int h = 0; h < HEADS; h++) m[h] = -1e30f;

    for (int i = st + lane; i < en; i += 32) {
        int s = g_esrc[i];
        if (HEADS == 4) {
            float4 av = ((const float4*)g_als)[s];
            m[0] = fmaxf(m[0], lrelu(av.x + ald[0]));
            m[1] = fmaxf(m[1], lrelu(av.y + ald[1]));
            m[2] = fmaxf(m[2], lrelu(av.z + ald[2]));
            m[3] = fmaxf(m[3], lrelu(av.w + ald[3]));
        } else {
            m[0] = fmaxf(m[0], lrelu(g_als[s] + ald[0]));
        }
    }
    #pragma unroll
    for (int h = 0; h < HEADS; h++)
        #pragma unroll
        for (int off = 16; off; off >>= 1)
            m[h] = fmaxf(m[h], __shfl_xor_sync(0xffffffffu, m[h], off));

    float ssum[HEADS];
    #pragma unroll
    for (int h = 0; h < HEADS; h++) ssum[h] = 0.f;

    if (HEADS == 4) {
        bool lo = lane < 16;
        float4 a0 = make_float4(0.f, 0.f, 0.f, 0.f), a1 = a0;
        for (int i = st; i < en; i++) {
            int s = g_esrc[i];
            float4 av = ((const float4*)g_als)[s];
            float ex0 = __expf(lrelu(av.x + ald[0]) - m[0]);
            float ex1 = __expf(lrelu(av.y + ald[1]) - m[1]);
            float ex2 = __expf(lrelu(av.z + ald[2]) - m[2]);
            float ex3 = __expf(lrelu(av.w + ald[3]) - m[3]);
            ssum[0] += ex0; ssum[1] += ex1; ssum[2] += ex2; ssum[3] += ex3;
            const float4* h4 = (const float4*)(hlin + (size_t)s * 256);
            float4 v0 = h4[lane], v1 = h4[32 + lane];
            float e01 = lo ? ex0 : ex1;
            float e23 = lo ? ex2 : ex3;
            a0.x += e01 * v0.x; a0.y += e01 * v0.y; a0.z += e01 * v0.z; a0.w += e01 * v0.w;
            a1.x += e23 * v1.x; a1.y += e23 * v1.y; a1.z += e23 * v1.z; a1.w += e23 * v1.w;
        }
        float s01 = lo ? ssum[0] : ssum[1];
        float s23 = lo ? ssum[2] : ssum[3];
        const float4* b4 = (const float4*)bias;
        float4 bb0 = b4[lane], bb1 = b4[32 + lane];
        float4 o0, o1;
        o0.x = a0.x / s01 + bb0.x; o0.y = a0.y / s01 + bb0.y;
        o0.z = a0.z / s01 + bb0.z; o0.w = a0.w / s01 + bb0.w;
        o1.x = a1.x / s23 + bb1.x; o1.y = a1.y / s23 + bb1.y;
        o1.z = a1.z / s23 + bb1.z; o1.w = a1.w / s23 + bb1.w;
        if (DOELU) {
            o0.x = o0.x > 0.f ? o0.x : __expf(o0.x) - 1.f;
            o0.y = o0.y > 0.f ? o0.y : __expf(o0.y) - 1.f;
            o0.z = o0.z > 0.f ? o0.z : __expf(o0.z) - 1.f;
            o0.w = o0.w > 0.f ? o0.w : __expf(o0.w) - 1.f;
            o1.x = o1.x > 0.f ? o1.x : __expf(o1.x) - 1.f;
            o1.y = o1.y > 0.f ? o1.y : __expf(o1.y) - 1.f;
            o1.z = o1.z > 0.f ? o1.z : __expf(o1.z) - 1.f;
            o1.w = o1.w > 0.f ? o1.w : __expf(o1.w) - 1.f;
        }
        float4* ho = (float4*)(hout + (size_t)n * 256);
        ho[lane] = o0;
        ho[32 + lane] = o1;
    } else {
        float2 a = make_float2(0.f, 0.f);
        for (int i = st; i < en; i++) {
            int s = g_esrc[i];
            float ex = __expf(lrelu(g_als[s] + ald[0]) - m[0]);
            ssum[0] += ex;
            const float2* h2 = (const float2*)(hlin + (size_t)s * 64);
            float2 v = h2[lane];
            a.x += ex * v.x;
            a.y += ex * v.y;
        }
        const float2* b2 = (const float2*)bias;
        float2 bb = b2[lane];
        float2 o;
        o.x = a.x / ssum[0] + bb.x;
        o.y = a.y / ssum[0] + bb.y;
        if (DOELU) {
            o.x = o.x > 0.f ? o.x : __expf(o.x) - 1.f;
            o.y = o.y > 0.f ? o.y : __expf(o.y) - 1.f;
        }
        ((float2*)(hout + (size_t)n * 64))[lane] = o;
    }

    for (int i = st + lane; i < en; i += 32) {
        int s = g_esrc[i];
        long long id = g_eid[i];
        if (HEADS == 4) {
            float4 av = ((const float4*)g_als)[s];
            att[id * 4 + 0] = __expf(lrelu(av.x + ald[0]) - m[0]) / ssum[0];
            att[id * 4 + 1] = __expf(lrelu(av.y + ald[1]) - m[1]) / ssum[1];
            att[id * 4 + 2] = __expf(lrelu(av.z + ald[2]) - m[2]) / ssum[2];
            att[id * 4 + 3] = __expf(lrelu(av.w + ald[3]) - m[3]) / ssum[3];
        } else {
            att[id] = __expf(lrelu(g_als[s] + ald[0]) - m[0]) / ssum[0];
        }
    }
}

// ---------------- global mean pool (sum + count) ----------------
__global__ void pool_k(const void* batch, const float* __restrict__ h3) {
    long long t = (long long)blockIdx.x * blockDim.x + threadIdx.x;
    if (t >= (long long)NN * DD) return;
    int n = (int)(t >> 6);
    int d = (int)(t & 63);
    int g = ld_idx(batch, n, g_is64_b);
    atomicAdd(&g_pool[g * DD + d], h3[t]);
    if (d == 0) atomicAdd(&g_cnt[g], 1.f);
}

// ---------------- classifier ----------------
__global__ void classifier_k(const float* __restrict__ Wc1, const float* __restrict__ bc1,
                             const float* __restrict__ Wc2, const float* __restrict__ bc2,
                             float* __restrict__ out) {
    __shared__ float hid[GG][33];
    int t = threadIdx.x;
    for (int idx = t; idx < GG * 32; idx += blockDim.x) {
        int g = idx >> 5, j = idx & 31;
        float inv = 1.f / fmaxf(g_cnt[g], 1.f);
        float s = bc1[j];
        #pragma unroll
        for (int d = 0; d < DD; d++)
            s += (g_pool[g * DD + d] * inv) * Wc1[d * 32 + j];
        hid[g][j] = fmaxf(s, 0.f);
    }
    __syncthreads();
    for (int idx = t; idx < GG * CC; idx += blockDim.x) {
        int g = idx / CC, c = idx % CC;
        float s = bc2[c];
        #pragma unroll
        for (int j = 0; j < 32; j++)
            s += hid[g][j] * Wc2[j * CC + c];
        out[g * CC + c] = s;
    }
}

// ---------------- launch ----------------
extern "C" void kernel_launch(void* const* d_in, const int* in_sizes, int n_in,
                              void* d_out, int out_size) {
    const float* x   = (const float*)d_in[0];
    const void*  ei  = d_in[1];
    const void*  bat = d_in[2];
    const float* W1  = (const float*)d_in[3];
    const float* as1 = (const float*)d_in[4];
    const float* ad1 = (const float*)d_in[5];
    const float* b1  = (const float*)d_in[6];
    const float* W2  = (const float*)d_in[7];
    const float* as2 = (const float*)d_in[8];
    const float* ad2 = (const float*)d_in[9];
    const float* b2  = (const float*)d_in[10];
    const float* W3  = (const float*)d_in[11];
    const float* as3 = (const float*)d_in[12];
    const float* ad3 = (const float*)d_in[13];
    const float* b3  = (const float*)d_in[14];
    const float* Wc1 = (const float*)d_in[15];
    const float* bc1 = (const float*)d_in[16];
    const float* Wc2 = (const float*)d_in[17];
    const float* bc2 = (const float*)d_in[18];

    float* out  = (float*)d_out;
    float* att1 = out + GG * CC;
    float* att2 = att1 + (size_t)ETOT * 4;
    float* att3 = att2 + (size_t)ETOT * 4;

    float *bufA, *bufB;
    cudaGetSymbolAddress((void**)&bufA, g_bufA);
    cudaGetSymbolAddress((void**)&bufB, g_bufB);

    const int NB_E = (ETOT + 255) / 256;
    const int NB_N = (NN + 255) / 256;
    const int NB_W = (NN * 32 + 255) / 256;   // one warp per node
    const int MB   = (NN + 127) / 128;        // 391 gemm row-blocks

    zero_k<<<NB_N, 256>>>(ei, bat);
    count_k<<<NB_E, 256>>>(ei);
    scan_k<<<1, 1024>>>();
    scatter_k<<<NB_E, 256>>>(ei);

    // Layer 1: h = x @ W1 -> [N, 256]
    gemm_tf32_k<<<dim3(2, MB), 256>>>(x, W1, bufA, NN, FF, 256);
    compute_al_k<4><<<NB_W, 256>>>(bufA, as1, ad1);
    aggregate_k<4, true><<<NB_W, 256>>>(bufA, b1, bufB, att1);

    // Layer 2
    gemm_tf32_k<<<dim3(2, MB), 256>>>(bufB, W2, bufA, NN, 256, 256);
    compute_al_k<4><<<NB_W, 256>>>(bufA, as2, ad2);
    aggregate_k<4, true><<<NB_W, 256>>>(bufA, b2, bufB, att2);

    // Layer 3: heads=1, D=64, no ELU
    gemm_tf32_k<<<dim3(1, MB), 256>>>(bufB, W3, bufA, NN, 256, 64);
    compute_al_k<1><<<NB_W, 256>>>(bufA, as3, ad3);
    aggregate_k<1, false><<<NB_W, 256>>>(bufA, b3, bufB, att3);

    // Pool + classify
    pool_k<<<(int)(((long long)NN * DD + 255) / 256), 256>>>(bat, bufB);
    classifier_k<<<1, 256>>>(Wc1, bc1, Wc2, bc2, out);
}

// round 5
// speedup vs baseline: 1.4595x; 1.4595x over previous
#include <cuda_runtime.h>
#include <cuda_bf16.h>
#include <cstdint>
#include <stdint.h>
#include <math.h>

// Problem constants
#define NN 50000
#define EE 800000
#define ETOT (EE + NN)   // 850000 (edges + self loops)
#define FF 128
#define DD 64
#define GG 32
#define CC 3

// ---------------- device scratch (static; no allocation allowed) ----------------
__device__ float g_bufA[(size_t)NN * 256];            // GEMM output (fp32)
__device__ float g_bufB[(size_t)NN * 256];            // layer-3 aggregate output (fp32)
__device__ __nv_bfloat16 g_Ahi[(size_t)NN * 256];     // GEMM A input hi
__device__ __nv_bfloat16 g_Alo[(size_t)NN * 256];     // GEMM A input lo
__device__ __nv_bfloat16 g_Whi[256 * 256];            // W transposed [N][K] hi
__device__ __nv_bfloat16 g_Wlo[256 * 256];            // W transposed [N][K] lo
__device__ float g_als[NN * 4];
__device__ float g_ald[NN * 4];
__device__ int   g_rowptr[NN + 1];
__device__ int   g_cursor[NN];
__device__ int   g_esrc[ETOT];
__device__ int   g_eid[ETOT];
__device__ float g_pool[GG * DD];
__device__ float g_cnt[GG];
__device__ int   g_is64_ei;
__device__ int   g_is64_b;

// ---------------- helpers ----------------
__device__ __forceinline__ float lrelu(float x) { return x > 0.f ? x : 0.2f * x; }

__device__ __forceinline__ int ld_idx(const void* p, long long i, int is64) {
    if (is64) return ((const int*)p)[2 * i];   // little-endian low word
    return ((const int*)p)[i];
}

__device__ __forceinline__ uint32_t smem_to_u32(const void* smem_ptr) {
    uint32_t addr;
    asm("{ .reg .u64 tmp; cvta.to.shared.u64 tmp, %1; cvt.u32.u64 %0, tmp; }"
        : "=r"(addr) : "l"(smem_ptr));
    return addr;
}

__device__ __forceinline__ void cp_async16(uint32_t dst, const void* src, int sz) {
    asm volatile("cp.async.ca.shared.global [%0], [%1], 16, %2;"
                 :: "r"(dst), "l"(src), "r"(sz));
}
__device__ __forceinline__ void cp_commit() {
    asm volatile("cp.async.commit_group;" ::: "memory");
}
template <int N>
__device__ __forceinline__ void cp_wait() {
    asm volatile("cp.async.wait_group %0;" :: "n"(N) : "memory");
}

__device__ __forceinline__ void ldsm_x4(uint32_t* r, uint32_t a) {
    asm volatile("ldmatrix.sync.aligned.m8n8.x4.shared.b16 {%0,%1,%2,%3}, [%4];"
                 : "=r"(r[0]), "=r"(r[1]), "=r"(r[2]), "=r"(r[3]) : "r"(a));
}

__device__ __forceinline__ void mma_bf16(float* d, const uint32_t* a, const uint32_t* b) {
    asm volatile(
        "mma.sync.aligned.m16n8k16.row.col.f32.bf16.bf16.f32 "
        "{%0,%1,%2,%3},{%4,%5,%6,%7},{%8,%9},{%0,%1,%2,%3};"
        : "+f"(d[0]), "+f"(d[1]), "+f"(d[2]), "+f"(d[3])
        : "r"(a[0]), "r"(a[1]), "r"(a[2]), "r"(a[3]), "r"(b[0]), "r"(b[1]));
}

// split fp32 -> bf16 hi + bf16 lo
__device__ __forceinline__ void bf16_split(float v, unsigned short& h, unsigned short& l) {
    __nv_bfloat16 hb = __float2bfloat16_rn(v);
    h = __bfloat16_as_ushort(hb);
    l = __bfloat16_as_ushort(__float2bfloat16_rn(v - __bfloat162float(hb)));
}

// ---------------- zero scratch + dtype detection ----------------
__global__ void zero_k(const void* ei, const void* batch) {
    int i = blockIdx.x * blockDim.x + threadIdx.x;
    if (i < NN) g_cursor[i] = 0;
    if (i < GG * DD) g_pool[i] = 0.f;
    if (i < GG) g_cnt[i] = 0.f;
    if (i == 0) {
        const int* p = (const int*)ei;
        bool z = true;
        #pragma unroll
        for (int j = 0; j < 16; j++) z = z && (p[2 * j + 1] == 0);
        g_is64_ei = z ? 1 : 0;
        const int* q = (const int*)batch;
        bool zb = true;
        #pragma unroll
        for (int j = 0; j < 16; j++) zb = zb && (q[NN - 1 - 2 * j] == 0);
        g_is64_b = zb ? 1 : 0;
    }
}

// ---------------- CSR build ----------------
__global__ void count_k(const void* ei) {
    long long e = (long long)blockIdx.x * blockDim.x + threadIdx.x;
    if (e >= ETOT) return;
    int is64 = g_is64_ei;
    int d = (e < EE) ? ld_idx(ei, (long long)EE + e, is64) : (int)(e - EE);
    atomicAdd(&g_cursor[d], 1);
}

__global__ void scan_k() {
    __shared__ int wsum[32];
    const int CH = 49;
    int t = threadIdx.x;
    int base = t * CH;
    int s = 0;
    for (int i = 0; i < CH; i++) {
        int idx = base + i;
        if (idx < NN) s += g_cursor[idx];
    }
    int lane = t & 31, w = t >> 5;
    int v = s;
    #pragma unroll
    for (int o = 1; o < 32; o <<= 1) {
        int u = __shfl_up_sync(0xffffffffu, v, o);
        if (lane >= o) v += u;
    }
    if (lane == 31) wsum[w] = v;
    __syncthreads();
    if (w == 0) {
        int x = wsum[lane];
        #pragma unroll
        for (int o = 1; o < 32; o <<= 1) {
            int u = __shfl_up_sync(0xffffffffu, x, o);
            if (lane >= o) x += u;
        }
        wsum[lane] = x;
    }
    __syncthreads();
    int excl = v - s + (w > 0 ? wsum[w - 1] : 0);
    for (int i = 0; i < CH; i++) {
        int idx = base + i;
        if (idx < NN) {
            int c = g_cursor[idx];
            g_rowptr[idx] = excl;
            g_cursor[idx] = excl;
            excl += c;
        }
    }
    if (t == 1023) g_rowptr[NN] = excl;
}

__global__ void scatter_k(const void* ei) {
    long long e = (long long)blockIdx.x * blockDim.x + threadIdx.x;
    if (e >= ETOT) return;
    int is64 = g_is64_ei;
    int s, d;
    if (e < EE) {
        s = ld_idx(ei, e, is64);
        d = ld_idx(ei, (long long)EE + e, is64);
    } else {
        s = d = (int)(e - EE);
    }
    int pos = atomicAdd(&g_cursor[d], 1);
    g_esrc[pos] = s;
    g_eid[pos]  = (int)e;
}

// ---------------- input converts ----------------
// x [NN*FF] fp32 -> g_Ahi/g_Alo (same layout)
__global__ void convertX_k(const float* __restrict__ x) {
    size_t i4 = (size_t)blockIdx.x * blockDim.x + threadIdx.x;
    if (i4 * 4 >= (size_t)NN * FF) return;
    float4 v = ((const float4*)x)[i4];
    unsigned short h[4], l[4];
    bf16_split(v.x, h[0], l[0]);
    bf16_split(v.y, h[1], l[1]);
    bf16_split(v.z, h[2], l[2]);
    bf16_split(v.w, h[3], l[3]);
    uint2 hv = make_uint2((uint32_t)h[0] | ((uint32_t)h[1] << 16),
                          (uint32_t)h[2] | ((uint32_t)h[3] << 16));
    uint2 lv = make_uint2((uint32_t)l[0] | ((uint32_t)l[1] << 16),
                          (uint32_t)l[2] | ((uint32_t)l[3] << 16));
    ((uint2*)g_Ahi)[i4] = hv;
    ((uint2*)g_Alo)[i4] = lv;
}

// W [K][N] fp32 -> g_Whi/g_Wlo transposed [N][K]
__global__ void convertW_k(const float* __restrict__ W, int K, int N) {
    int idx = blockIdx.x * blockDim.x + threadIdx.x;
    if (idx >= K * N) return;
    int n = idx / K, k = idx - n * K;
    float v = W[(size_t)k * N + n];
    unsigned short h, l;
    bf16_split(v, h, l);
    g_Whi[idx] = __ushort_as_bfloat16(h);
    g_Wlo[idx] = __ushort_as_bfloat16(l);
}

// ---------------- bf16 3-split mma.sync GEMM: C[M,Nc] = A[M,K] @ Wt[Nc,K]^T ----------------
// Block 128 x N_TILE, 256 threads, BK=32, double-buffered cp.async, XOR-swizzled smem.
template <int N_TILE>
__global__ void __launch_bounds__(256) gemm_bf16_k(
    const __nv_bfloat16* __restrict__ Ahi, const __nv_bfloat16* __restrict__ Alo,
    const __nv_bfloat16* __restrict__ Bhi, const __nv_bfloat16* __restrict__ Blo,
    float* __restrict__ Cm, int M, int K, int Nc) {
    constexpr int WN_T  = N_TILE / 32;    // warps along N (4 or 2)
    constexpr int WM_T  = 8 / WN_T;       // warps along M (2 or 4)
    constexpr int WM_SZ = 128 / WM_T;     // 64 or 32
    constexpr int MT    = WM_SZ / 16;     // 4 or 2
    constexpr int ABYTES = 128 * 64;      // 8KB (one A matrix per stage)
    constexpr int BBYTES = N_TILE * 64;
    constexpr int STAGE  = 2 * ABYTES + 2 * BBYTES;

    extern __shared__ char sm[];
    uint32_t sbase = smem_to_u32(sm);

    int tid = threadIdx.x;
    int warp = tid >> 5, lane = tid & 31;
    int rowBase = blockIdx.y * 128;
    int colBase = blockIdx.x * N_TILE;
    int wm = warp % WM_T, wn = warp / WM_T;

    float acc[MT][4][4];
    #pragma unroll
    for (int i = 0; i < MT; i++)
        #pragma unroll
        for (int j = 0; j < 4; j++)
            #pragma unroll
            for (int q = 0; q < 4; q++) acc[i][j][q] = 0.f;

    auto load_chunk = [&](int c, int s) {
        int k0 = c * 32;
        uint32_t so = sbase + s * STAGE;
        // A: 512 16B-units per matrix, 2 per thread
        #pragma unroll
        for (int j = 0; j < 2; j++) {
            int uid = tid * 2 + j;
            int row = uid >> 2, u = uid & 3;
            uint32_t d = so + row * 64 + ((u ^ ((row >> 1) & 3)) * 16);
            size_t goff = (size_t)(rowBase + row) * K + k0 + u * 8;
            int sz = (rowBase + row < M) ? 16 : 0;
            cp_async16(d, Ahi + goff, sz);
            cp_async16(d + ABYTES, Alo + goff, sz);
        }
        // B: N_TILE*4 units
        #pragma unroll
        for (int j = 0; j < (N_TILE * 4) / 256; j++) {
            int uid = tid + 256 * j;
            int row = uid >> 2, u = uid & 3;
            uint32_t d = so + 2 * ABYTES + row * 64 + ((u ^ ((row >> 1) & 3)) * 16);
            size_t goff = (size_t)(colBase + row) * K + k0 + u * 8;
            cp_async16(d, Bhi + goff, 16);
            cp_async16(d + BBYTES, Blo + goff, 16);
        }
    };

    auto compute = [&](int s) {
        uint32_t aB = sbase + s * STAGE;
        uint32_t bB = aB + 2 * ABYTES;
        #pragma unroll
        for (int k16 = 0; k16 < 2; k16++) {
            int usel = k16 * 2 + (lane >> 4);
            uint32_t ahi[MT][4], alo[MT][4];
            #pragma unroll
            for (int mt = 0; mt < MT; mt++) {
                int row = wm * WM_SZ + mt * 16 + (lane & 15);
                uint32_t addr = aB + row * 64 + ((usel ^ ((row >> 1) & 3)) * 16);
                ldsm_x4(ahi[mt], addr);
                ldsm_x4(alo[mt], addr + ABYTES);
            }
            uint32_t bhi[4][2], blo[4][2];
            #pragma unroll
            for (int half = 0; half < 2; half++) {
                int row = wn * 32 + half * 16 + (lane & 15);
                uint32_t addr = bB + row * 64 + ((usel ^ ((row >> 1) & 3)) * 16);
                uint32_t r[4], r2[4];
                ldsm_x4(r, addr);
                ldsm_x4(r2, addr + BBYTES);
                bhi[half * 2 + 0][0] = r[0];  bhi[half * 2 + 0][1] = r[2];
                bhi[half * 2 + 1][0] = r[1];  bhi[half * 2 + 1][1] = r[3];
                blo[half * 2 + 0][0] = r2[0]; blo[half * 2 + 0][1] = r2[2];
                blo[half * 2 + 1][0] = r2[1]; blo[half * 2 + 1][1] = r2[3];
            }
            #pragma unroll
            for (int mt = 0; mt < MT; mt++)
                #pragma unroll
                for (int nt = 0; nt < 4; nt++) {
                    mma_bf16(acc[mt][nt], ahi[mt], bhi[nt]);
                    mma_bf16(acc[mt][nt], ahi[mt], blo[nt]);
                    mma_bf16(acc[mt][nt], alo[mt], bhi[nt]);
                }
        }
    };

    int nch = K >> 5;
    load_chunk(0, 0);
    cp_commit();
    for (int c = 0; c < nch; c++) {
        if (c + 1 < nch) {
            load_chunk(c + 1, (c + 1) & 1);
            cp_commit();
            cp_wait<1>();
        } else {
            cp_wait<0>();
        }
        __syncthreads();
        compute(c & 1);
        __syncthreads();
    }

    // epilogue
    #pragma unroll
    for (int mt = 0; mt < MT; mt++) {
        int r0 = rowBase + wm * WM_SZ + mt * 16 + (lane >> 2);
        #pragma unroll
        for (int nt = 0; nt < 4; nt++) {
            int col = colBase + wn * 32 + nt * 8 + (lane & 3) * 2;
            if (r0 < M)
                *(float2*)(Cm + (size_t)r0 * Nc + col) =
                    make_float2(acc[mt][nt][0], acc[mt][nt][1]);
            if (r0 + 8 < M)
                *(float2*)(Cm + (size_t)(r0 + 8) * Nc + col) =
                    make_float2(acc[mt][nt][2], acc[mt][nt][3]);
        }
    }
}

// ---------------- per-node attention logits al_s, al_d ----------------
template <int HEADS>
__global__ void __launch_bounds__(256) compute_al_k(const float* __restrict__ h,
                                                    const float* __restrict__ a_s,
                                                    const float* __restrict__ a_d) {
    constexpr int HD = HEADS * DD;
    constexpr int LPH = 32 / HEADS;
    constexpr int CPL = DD / LPH;
    int wid = (blockIdx.x * blockDim.x + threadIdx.x) >> 5;
    int lane = threadIdx.x & 31;
    if (wid >= NN) return;
    int hh = lane / LPH;
    int j = lane % LPH;
    const float* row = h + (size_t)wid * HD + hh * DD + j * CPL;
    const float* asr = a_s + hh * DD + j * CPL;
    const float* adr = a_d + hh * DD + j * CPL;
    float ss = 0.f, sd = 0.f;
    #pragma unroll
    for (int c = 0; c < CPL; c++) {
        float v = row[c];
        ss += v * asr[c];
        sd += v * adr[c];
    }
    #pragma unroll
    for (int off = LPH / 2; off; off >>= 1) {
        ss += __shfl_down_sync(0xffffffffu, ss, off);
        sd += __shfl_down_sync(0xffffffffu, sd, off);
    }
    if (j == 0) {
        g_als[wid * HEADS + hh] = ss;
        g_ald[wid * HEADS + hh] = sd;
    }
}

// ---------------- GAT aggregation (warp per dst) ----------------
// TO_BF16: write bf16 hi/lo (next GEMM input) instead of fp32.
template <int HEADS, bool DOELU, bool TO_BF16>
__global__ void __launch_bounds__(256) aggregate_k(const float* __restrict__ hlin,
                                                   const float* __restrict__ bias,
                                                   float* __restrict__ hout,
                                                   float* __restrict__ att) {
    int wid = (blockIdx.x * blockDim.x + threadIdx.x) >> 5;
    int lane = threadIdx.x & 31;
    if (wid >= NN) return;
    int n = wid;
    int st = g_rowptr[n], en = g_rowptr[n + 1];

    float ald[HEADS];
    if (HEADS == 4) {
        float4 v = ((const float4*)g_ald)[n];
        ald[0] = v.x; ald[1] = v.y; ald[2] = v.z; ald[3] = v.w;
    } else {
        ald[0] = g_ald[n];
    }

    float m[HEADS];
    #pragma unroll
    for (int h = 0; h < HEADS; h++) m[h] = -1e30f;

    for (int i = st + lane; i < en; i += 32) {
        int s = g_esrc[i];
        if (HEADS == 4) {
            float4 av = ((const float4*)g_als)[s];
            m[0] = fmaxf(m[0], lrelu(av.x + ald[0]));
            m[1] = fmaxf(m[1], lrelu(av.y + ald[1]));
            m[2] = fmaxf(m[2], lrelu(av.z + ald[2]));
            m[3] = fmaxf(m[3], lrelu(av.w + ald[3]));
        } else {
            m[0] = fmaxf(m[0], lrelu(g_als[s] + ald[0]));
        }
    }
    #pragma unroll
    for (int h = 0; h < HEADS; h++)
        #pragma unroll
        for (int off = 16; off; off >>= 1)
            m[h] = fmaxf(m[h], __shfl_xor_sync(0xffffffffu, m[h], off));

    float ssum[HEADS];
    #pragma unroll
    for (int h = 0; h < HEADS; h++) ssum[h] = 0.f;

    if (HEADS == 4) {
        bool lo = lane < 16;
        float4 a0 = make_float4(0.f, 0.f, 0.f, 0.f), a1 = a0;
        for (int i = st; i < en; i++) {
            int s = g_esrc[i];
            float4 av = ((const float4*)g_als)[s];
            float ex0 = __expf(lrelu(av.x + ald[0]) - m[0]);
            float ex1 = __expf(lrelu(av.y + ald[1]) - m[1]);
            float ex2 = __expf(lrelu(av.z + ald[2]) - m[2]);
            float ex3 = __expf(lrelu(av.w + ald[3]) - m[3]);
            ssum[0] += ex0; ssum[1] += ex1; ssum[2] += ex2; ssum[3] += ex3;
            const float4* h4 = (const float4*)(hlin + (size_t)s * 256);
            float4 v0 = h4[lane], v1 = h4[32 + lane];
            float e01 = lo ? ex0 : ex1;
            float e23 = lo ? ex2 : ex3;
            a0.x += e01 * v0.x; a0.y += e01 * v0.y; a0.z += e01 * v0.z; a0.w += e01 * v0.w;
            a1.x += e23 * v1.x; a1.y += e23 * v1.y; a1.z += e23 * v1.z; a1.w += e23 * v1.w;
        }
        float s01 = lo ? ssum[0] : ssum[1];
        float s23 = lo ? ssum[2] : ssum[3];
        const float4* b4 = (const float4*)bias;
        float4 bb0 = b4[lane], bb1 = b4[32 + lane];
        float4 o0, o1;
        o0.x = a0.x / s01 + bb0.x; o0.y = a0.y / s01 + bb0.y;
        o0.z = a0.z / s01 + bb0.z; o0.w = a0.w / s01 + bb0.w;
        o1.x = a1.x / s23 + bb1.x; o1.y = a1.y / s23 + bb1.y;
        o1.z = a1.z / s23 + bb1.z; o1.w = a1.w / s23 + bb1.w;
        if (DOELU) {
            o0.x = o0.x > 0.f ? o0.x : __expf(o0.x) - 1.f;
            o0.y = o0.y > 0.f ? o0.y : __expf(o0.y) - 1.f;
            o0.z = o0.z > 0.f ? o0.z : __expf(o0.z) - 1.f;
            o0.w = o0.w > 0.f ? o0.w : __expf(o0.w) - 1.f;
            o1.x = o1.x > 0.f ? o1.x : __expf(o1.x) - 1.f;
            o1.y = o1.y > 0.f ? o1.y : __expf(o1.y) - 1.f;
            o1.z = o1.z > 0.f ? o1.z : __expf(o1.z) - 1.f;
            o1.w = o1.w > 0.f ? o1.w : __expf(o1.w) - 1.f;
        }
        if (TO_BF16) {
            unsigned short h0[4], l0[4], h1[4], l1[4];
            bf16_split(o0.x, h0[0], l0[0]); bf16_split(o0.y, h0[1], l0[1]);
            bf16_split(o0.z, h0[2], l0[2]); bf16_split(o0.w, h0[3], l0[3]);
            bf16_split(o1.x, h1[0], l1[0]); bf16_split(o1.y, h1[1], l1[1]);
            bf16_split(o1.z, h1[2], l1[2]); bf16_split(o1.w, h1[3], l1[3]);
            uint2* dh0 = (uint2*)(g_Ahi + (size_t)n * 256 + lane * 4);
            uint2* dl0 = (uint2*)(g_Alo + (size_t)n * 256 + lane * 4);
            uint2* dh1 = (uint2*)(g_Ahi + (size_t)n * 256 + 128 + lane * 4);
            uint2* dl1 = (uint2*)(g_Alo + (size_t)n * 256 + 128 + lane * 4);
            *dh0 = make_uint2((uint32_t)h0[0] | ((uint32_t)h0[1] << 16),
                              (uint32_t)h0[2] | ((uint32_t)h0[3] << 16));
            *dl0 = make_uint2((uint32_t)l0[0] | ((uint32_t)l0[1] << 16),
                              (uint32_t)l0[2] | ((uint32_t)l0[3] << 16));
            *dh1 = make_uint2((uint32_t)h1[0] | ((uint32_t)h1[1] << 16),
                              (uint32_t)h1[2] | ((uint32_t)h1[3] << 16));
            *dl1 = make_uint2((uint32_t)l1[0] | ((uint32_t)l1[1] << 16),
                              (uint32_t)l1[2] | ((uint32_t)l1[3] << 16));
        } else {
            float4* ho = (float4*)(hout + (size_t)n * 256);
            ho[lane] = o0;
            ho[32 + lane] = o1;
        }
    } else {
        float2 a = make_float2(0.f, 0.f);
        for (int i = st; i < en; i++) {
            int s = g_esrc[i];
            float ex = __expf(lrelu(g_als[s] + ald[0]) - m[0]);
            ssum[0] += ex;
            const float2* h2 = (const float2*)(hlin + (size_t)s * 64);
            float2 v = h2[lane];
            a.x += ex * v.x;
            a.y += ex * v.y;
        }
        const float2* b2 = (const float2*)bias;
        float2 bb = b2[lane];
        float2 o;
        o.x = a.x / ssum[0] + bb.x;
        o.y = a.y / ssum[0] + bb.y;
        if (DOELU) {
            o.x = o.x > 0.f ? o.x : __expf(o.x) - 1.f;
            o.y = o.y > 0.f ? o.y : __expf(o.y) - 1.f;
        }
        ((float2*)(hout + (size_t)n * 64))[lane] = o;
    }

    for (int i = st + lane; i < en; i += 32) {
        int s = g_esrc[i];
        long long id = g_eid[i];
        if (HEADS == 4) {
            float4 av = ((const float4*)g_als)[s];
            att[id * 4 + 0] = __expf(lrelu(av.x + ald[0]) - m[0]) / ssum[0];
            att[id * 4 + 1] = __expf(lrelu(av.y + ald[1]) - m[1]) / ssum[1];
            att[id * 4 + 2] = __expf(lrelu(av.z + ald[2]) - m[2]) / ssum[2];
            att[id * 4 + 3] = __expf(lrelu(av.w + ald[3]) - m[3]) / ssum[3];
        } else {
            att[id] = __expf(lrelu(g_als[s] + ald[0]) - m[0]) / ssum[0];
        }
    }
}

// ---------------- global mean pool (sum + count) ----------------
__global__ void pool_k(const void* batch, const float* __restrict__ h3) {
    long long t = (long long)blockIdx.x * blockDim.x + threadIdx.x;
    if (t >= (long long)NN * DD) return;
    int n = (int)(t >> 6);
    int d = (int)(t & 63);
    int g = ld_idx(batch, n, g_is64_b);
    atomicAdd(&g_pool[g * DD + d], h3[t]);
    if (d == 0) atomicAdd(&g_cnt[g], 1.f);
}

// ---------------- classifier ----------------
__global__ void classifier_k(const float* __restrict__ Wc1, const float* __restrict__ bc1,
                             const float* __restrict__ Wc2, const float* __restrict__ bc2,
                             float* __restrict__ out) {
    __shared__ float hid[GG][33];
    int t = threadIdx.x;
    for (int idx = t; idx < GG * 32; idx += blockDim.x) {
        int g = idx >> 5, j = idx & 31;
        float inv = 1.f / fmaxf(g_cnt[g], 1.f);
        float s = bc1[j];
        #pragma unroll
        for (int d = 0; d < DD; d++)
            s += (g_pool[g * DD + d] * inv) * Wc1[d * 32 + j];
        hid[g][j] = fmaxf(s, 0.f);
    }
    __syncthreads();
    for (int idx = t; idx < GG * CC; idx += blockDim.x) {
        int g = idx / CC, c = idx % CC;
        float s = bc2[c];
        #pragma unroll
        for (int j = 0; j < 32; j++)
            s += hid[g][j] * Wc2[j * CC + c];
        out[g * CC + c] = s;
    }
}

// ---------------- launch ----------------
extern "C" void kernel_launch(void* const* d_in, const int* in_sizes, int n_in,
                              void* d_out, int out_size) {
    const float* x   = (const float*)d_in[0];
    const void*  ei  = d_in[1];
    const void*  bat = d_in[2];
    const float* W1  = (const float*)d_in[3];
    const float* as1 = (const float*)d_in[4];
    const float* ad1 = (const float*)d_in[5];
    const float* b1  = (const float*)d_in[6];
    const float* W2  = (const float*)d_in[7];
    const float* as2 = (const float*)d_in[8];
    const float* ad2 = (const float*)d_in[9];
    const float* b2  = (const float*)d_in[10];
    const float* W3  = (const float*)d_in[11];
    const float* as3 = (const float*)d_in[12];
    const float* ad3 = (const float*)d_in[13];
    const float* b3  = (const float*)d_in[14];
    const float* Wc1 = (const float*)d_in[15];
    const float* bc1 = (const float*)d_in[16];
    const float* Wc2 = (const float*)d_in[17];
    const float* bc2 = (const float*)d_in[18];

    float* out  = (float*)d_out;
    float* att1 = out + GG * CC;
    float* att2 = att1 + (size_t)ETOT * 4;
    float* att3 = att2 + (size_t)ETOT * 4;

    float *bufA, *bufB;
    cudaGetSymbolAddress((void**)&bufA, g_bufA);
    cudaGetSymbolAddress((void**)&bufB, g_bufB);
    __nv_bfloat16 *Ahi, *Alo, *Whi, *Wlo;
    cudaGetSymbolAddress((void**)&Ahi, g_Ahi);
    cudaGetSymbolAddress((void**)&Alo, g_Alo);
    cudaGetSymbolAddress((void**)&Whi, g_Whi);
    cudaGetSymbolAddress((void**)&Wlo, g_Wlo);

    const int NB_E = (ETOT + 255) / 256;
    const int NB_N = (NN + 255) / 256;
    const int NB_W = (NN * 32 + 255) / 256;   // one warp per node
    const int MB   = (NN + 127) / 128;        // 391 gemm row-blocks

    const int SMEM128 = 2 * (2 * 128 * 64 + 2 * 128 * 64);  // 65536
    const int SMEM64  = 2 * (2 * 128 * 64 + 2 * 64 * 64);   // 49152
    cudaFuncSetAttribute(gemm_bf16_k<128>, cudaFuncAttributeMaxDynamicSharedMemorySize, SMEM128);
    cudaFuncSetAttribute(gemm_bf16_k<64>,  cudaFuncAttributeMaxDynamicSharedMemorySize, SMEM64);

    zero_k<<<NB_N, 256>>>(ei, bat);
    count_k<<<NB_E, 256>>>(ei);
    scan_k<<<1, 1024>>>();
    scatter_k<<<NB_E, 256>>>(ei);

    // Layer 1: h = x @ W1 -> [N, 256]
    convertX_k<<<(NN * FF / 4 + 255) / 256, 256>>>(x);
    convertW_k<<<(FF * 256 + 255) / 256, 256>>>(W1, FF, 256);
    gemm_bf16_k<128><<<dim3(2, MB), 256, SMEM128>>>(Ahi, Alo, Whi, Wlo, bufA, NN, FF, 256);
    compute_al_k<4><<<NB_W, 256>>>(bufA, as1, ad1);
    aggregate_k<4, true, true><<<NB_W, 256>>>(bufA, b1, bufB, att1);

    // Layer 2
    convertW_k<<<(256 * 256 + 255) / 256, 256>>>(W2, 256, 256);
    gemm_bf16_k<128><<<dim3(2, MB), 256, SMEM128>>>(Ahi, Alo, Whi, Wlo, bufA, NN, 256, 256);
    compute_al_k<4><<<NB_W, 256>>>(bufA, as2, ad2);
    aggregate_k<4, true, true><<<NB_W, 256>>>(bufA, b2, bufB, att2);

    // Layer 3: heads=1, D=64, no ELU
    convertW_k<<<(256 * 64 + 255) / 256, 256>>>(W3, 256, 64);
    gemm_bf16_k<64><<<dim3(1, MB), 256, SMEM64>>>(Ahi, Alo, Whi, Wlo, bufA, NN, 256, 64);
    compute_al_k<1><<<NB_W, 256>>>(bufA, as3, ad3);
    aggregate_k<1, false, false><<<NB_W, 256>>>(bufA, b3, bufB, att3);

    // Pool + classify
    pool_k<<<(int)(((long long)NN * DD + 255) / 256), 256>>>(bat, bufB);
    classifier_k<<<1, 256>>>(Wc1, bc1, Wc2, bc2, out);
}

// round 6
// speedup vs baseline: 1.5714x; 1.0766x over previous
#include <cuda_runtime.h>
#include <cuda_bf16.h>
#include <cstdint>
#include <stdint.h>
#include <math.h>

// Problem constants
#define NN 50000
#define EE 800000
#define ETOT (EE + NN)   // 850000 (edges + self loops)
#define FF 128
#define DD 64
#define GG 32
#define CC 3

// ---------------- device scratch (static; no allocation allowed) ----------------
__device__ float g_bufA[(size_t)NN * 256];            // GEMM output (fp32)
__device__ float g_bufB[(size_t)NN * 256];            // layer-3 aggregate output (fp32)
__device__ __nv_bfloat16 g_Ahi[(size_t)NN * 256];     // GEMM A input hi
__device__ __nv_bfloat16 g_Alo[(size_t)NN * 256];     // GEMM A input lo
__device__ __nv_bfloat16 g_Whi[256 * 256];            // W transposed [N][K] hi
__device__ __nv_bfloat16 g_Wlo[256 * 256];            // W transposed [N][K] lo
__device__ float g_als[NN * 4];
__device__ float g_ald[NN * 4];
__device__ int   g_rowptr[NN + 1];
__device__ int   g_cursor[NN];
__device__ int   g_esrc[ETOT];
__device__ int   g_eid[ETOT];
__device__ float g_pool[GG * DD];
__device__ float g_cnt[GG];
__device__ int   g_is64_ei;
__device__ int   g_is64_b;

// ---------------- helpers ----------------
__device__ __forceinline__ float lrelu(float x) { return x > 0.f ? x : 0.2f * x; }

__device__ __forceinline__ int ld_idx(const void* p, long long i, int is64) {
    if (is64) return ((const int*)p)[2 * i];   // little-endian low word
    return ((const int*)p)[i];
}

__device__ __forceinline__ uint32_t smem_to_u32(const void* smem_ptr) {
    uint32_t addr;
    asm("{ .reg .u64 tmp; cvta.to.shared.u64 tmp, %1; cvt.u32.u64 %0, tmp; }"
        : "=r"(addr) : "l"(smem_ptr));
    return addr;
}

__device__ __forceinline__ void cp_async16(uint32_t dst, const void* src, int sz) {
    asm volatile("cp.async.ca.shared.global [%0], [%1], 16, %2;"
                 :: "r"(dst), "l"(src), "r"(sz));
}
__device__ __forceinline__ void cp_commit() {
    asm volatile("cp.async.commit_group;" ::: "memory");
}
template <int N>
__device__ __forceinline__ void cp_wait() {
    asm volatile("cp.async.wait_group %0;" :: "n"(N) : "memory");
}

__device__ __forceinline__ void ldsm_x4(uint32_t* r, uint32_t a) {
    asm volatile("ldmatrix.sync.aligned.m8n8.x4.shared.b16 {%0,%1,%2,%3}, [%4];"
                 : "=r"(r[0]), "=r"(r[1]), "=r"(r[2]), "=r"(r[3]) : "r"(a));
}

__device__ __forceinline__ void mma_bf16(float* d, const uint32_t* a, const uint32_t* b) {
    asm volatile(
        "mma.sync.aligned.m16n8k16.row.col.f32.bf16.bf16.f32 "
        "{%0,%1,%2,%3},{%4,%5,%6,%7},{%8,%9},{%0,%1,%2,%3};"
        : "+f"(d[0]), "+f"(d[1]), "+f"(d[2]), "+f"(d[3])
        : "r"(a[0]), "r"(a[1]), "r"(a[2]), "r"(a[3]), "r"(b[0]), "r"(b[1]));
}

// split fp32 -> bf16 hi + bf16 lo
__device__ __forceinline__ void bf16_split(float v, unsigned short& h, unsigned short& l) {
    __nv_bfloat16 hb = __float2bfloat16_rn(v);
    h = __bfloat16_as_ushort(hb);
    l = __bfloat16_as_ushort(__float2bfloat16_rn(v - __bfloat162float(hb)));
}

// ---------------- zero scratch + dtype detection ----------------
__global__ void zero_k(const void* ei, const void* batch) {
    int i = blockIdx.x * blockDim.x + threadIdx.x;
    if (i < NN) g_cursor[i] = 0;
    if (i < GG * DD) g_pool[i] = 0.f;
    if (i < GG) g_cnt[i] = 0.f;
    if (i == 0) {
        const int* p = (const int*)ei;
        bool z = true;
        #pragma unroll
        for (int j = 0; j < 16; j++) z = z && (p[2 * j + 1] == 0);
        g_is64_ei = z ? 1 : 0;
        const int* q = (const int*)batch;
        bool zb = true;
        #pragma unroll
        for (int j = 0; j < 16; j++) zb = zb && (q[NN - 1 - 2 * j] == 0);
        g_is64_b = zb ? 1 : 0;
    }
}

__global__ void zeroAL_k(int n) {
    int i = blockIdx.x * blockDim.x + threadIdx.x;
    if (i < n) { g_als[i] = 0.f; g_ald[i] = 0.f; }
}

// ---------------- CSR build ----------------
__global__ void count_k(const void* ei) {
    long long e = (long long)blockIdx.x * blockDim.x + threadIdx.x;
    if (e >= ETOT) return;
    int is64 = g_is64_ei;
    int d = (e < EE) ? ld_idx(ei, (long long)EE + e, is64) : (int)(e - EE);
    atomicAdd(&g_cursor[d], 1);
}

__global__ void scan_k() {
    __shared__ int wsum[32];
    const int CH = 49;
    int t = threadIdx.x;
    int base = t * CH;
    int s = 0;
    for (int i = 0; i < CH; i++) {
        int idx = base + i;
        if (idx < NN) s += g_cursor[idx];
    }
    int lane = t & 31, w = t >> 5;
    int v = s;
    #pragma unroll
    for (int o = 1; o < 32; o <<= 1) {
        int u = __shfl_up_sync(0xffffffffu, v, o);
        if (lane >= o) v += u;
    }
    if (lane == 31) wsum[w] = v;
    __syncthreads();
    if (w == 0) {
        int x = wsum[lane];
        #pragma unroll
        for (int o = 1; o < 32; o <<= 1) {
            int u = __shfl_up_sync(0xffffffffu, x, o);
            if (lane >= o) x += u;
        }
        wsum[lane] = x;
    }
    __syncthreads();
    int excl = v - s + (w > 0 ? wsum[w - 1] : 0);
    for (int i = 0; i < CH; i++) {
        int idx = base + i;
        if (idx < NN) {
            int c = g_cursor[idx];
            g_rowptr[idx] = excl;
            g_cursor[idx] = excl;
            excl += c;
        }
    }
    if (t == 1023) g_rowptr[NN] = excl;
}

__global__ void scatter_k(const void* ei) {
    long long e = (long long)blockIdx.x * blockDim.x + threadIdx.x;
    if (e >= ETOT) return;
    int is64 = g_is64_ei;
    int s, d;
    if (e < EE) {
        s = ld_idx(ei, e, is64);
        d = ld_idx(ei, (long long)EE + e, is64);
    } else {
        s = d = (int)(e - EE);
    }
    int pos = atomicAdd(&g_cursor[d], 1);
    g_esrc[pos] = s;
    g_eid[pos]  = (int)e;
}

// ---------------- input converts ----------------
__global__ void convertX_k(const float* __restrict__ x) {
    size_t i4 = (size_t)blockIdx.x * blockDim.x + threadIdx.x;
    if (i4 * 4 >= (size_t)NN * FF) return;
    float4 v = ((const float4*)x)[i4];
    unsigned short h[4], l[4];
    bf16_split(v.x, h[0], l[0]);
    bf16_split(v.y, h[1], l[1]);
    bf16_split(v.z, h[2], l[2]);
    bf16_split(v.w, h[3], l[3]);
    uint2 hv = make_uint2((uint32_t)h[0] | ((uint32_t)h[1] << 16),
                          (uint32_t)h[2] | ((uint32_t)h[3] << 16));
    uint2 lv = make_uint2((uint32_t)l[0] | ((uint32_t)l[1] << 16),
                          (uint32_t)l[2] | ((uint32_t)l[3] << 16));
    ((uint2*)g_Ahi)[i4] = hv;
    ((uint2*)g_Alo)[i4] = lv;
}

// W [K][N] fp32 -> g_Whi/g_Wlo transposed [N][K]
__global__ void convertW_k(const float* __restrict__ W, int K, int N) {
    int idx = blockIdx.x * blockDim.x + threadIdx.x;
    if (idx >= K * N) return;
    int n = idx / K, k = idx - n * K;
    float v = W[(size_t)k * N + n];
    unsigned short h, l;
    bf16_split(v, h, l);
    g_Whi[idx] = __ushort_as_bfloat16(h);
    g_Wlo[idx] = __ushort_as_bfloat16(l);
}

// ---------------- bf16 3-split mma.sync GEMM + fused attention logits ----------------
// Block 128 x N_TILE, THREADS threads (warp tile 32x32), BK=32, double-buffered cp.async.
// Epilogue also computes als/ald = h . a_src / a_dst per row via quad-reduce + atomics.
template <int N_TILE, int THREADS, int HEADS>
__global__ void __launch_bounds__(THREADS) gemm_bf16_k(
    const __nv_bfloat16* __restrict__ Ahi, const __nv_bfloat16* __restrict__ Alo,
    const __nv_bfloat16* __restrict__ Bhi, const __nv_bfloat16* __restrict__ Blo,
    float* __restrict__ Cm,
    const float* __restrict__ a_src, const float* __restrict__ a_dst,
    int M, int K, int Nc) {
    constexpr int ABYTES = 128 * 64;          // 8KB per A matrix per stage
    constexpr int BBYTES = N_TILE * 64;
    constexpr int STAGE  = 2 * ABYTES + 2 * BBYTES;

    extern __shared__ char sm[];
    uint32_t sbase = smem_to_u32(sm);

    int tid = threadIdx.x;
    int warp = tid >> 5, lane = tid & 31;
    int rowBase = blockIdx.y * 128;
    int colBase = blockIdx.x * N_TILE;
    int wm = warp & 3;          // 4 warps along M (32 rows each)
    int wn = warp >> 2;         // N_TILE/32 warps along N

    float acc[2][4][4];
    #pragma unroll
    for (int i = 0; i < 2; i++)
        #pragma unroll
        for (int j = 0; j < 4; j++)
            #pragma unroll
            for (int q = 0; q < 4; q++) acc[i][j][q] = 0.f;

    auto load_chunk = [&](int c, int s) {
        int k0 = c * 32;
        uint32_t so = sbase + s * STAGE;
        #pragma unroll
        for (int u = tid; u < 512; u += THREADS) {
            int row = u >> 2, q = u & 3;
            uint32_t d = so + row * 64 + ((q ^ ((row >> 1) & 3)) * 16);
            size_t goff = (size_t)(rowBase + row) * K + k0 + q * 8;
            int sz = (rowBase + row < M) ? 16 : 0;
            cp_async16(d, Ahi + goff, sz);
            cp_async16(d + ABYTES, Alo + goff, sz);
        }
        #pragma unroll
        for (int u = tid; u < N_TILE * 4; u += THREADS) {
            int row = u >> 2, q = u & 3;
            uint32_t d = so + 2 * ABYTES + row * 64 + ((q ^ ((row >> 1) & 3)) * 16);
            size_t goff = (size_t)(colBase + row) * K + k0 + q * 8;
            cp_async16(d, Bhi + goff, 16);
            cp_async16(d + BBYTES, Blo + goff, 16);
        }
    };

    auto compute = [&](int s) {
        uint32_t aB = sbase + s * STAGE;
        uint32_t bB = aB + 2 * ABYTES;
        #pragma unroll
        for (int k16 = 0; k16 < 2; k16++) {
            int usel = k16 * 2 + (lane >> 4);
            uint32_t ahi[2][4], alo[2][4];
            #pragma unroll
            for (int mt = 0; mt < 2; mt++) {
                int row = wm * 32 + mt * 16 + (lane & 15);
                uint32_t addr = aB + row * 64 + ((usel ^ ((row >> 1) & 3)) * 16);
                ldsm_x4(ahi[mt], addr);
                ldsm_x4(alo[mt], addr + ABYTES);
            }
            uint32_t bhi[4][2], blo[4][2];
            #pragma unroll
            for (int half = 0; half < 2; half++) {
                int row = wn * 32 + half * 16 + (lane & 15);
                uint32_t addr = bB + row * 64 + ((usel ^ ((row >> 1) & 3)) * 16);
                uint32_t r[4], r2[4];
                ldsm_x4(r, addr);
                ldsm_x4(r2, addr + BBYTES);
                bhi[half * 2 + 0][0] = r[0];  bhi[half * 2 + 0][1] = r[2];
                bhi[half * 2 + 1][0] = r[1];  bhi[half * 2 + 1][1] = r[3];
                blo[half * 2 + 0][0] = r2[0]; blo[half * 2 + 0][1] = r2[2];
                blo[half * 2 + 1][0] = r2[1]; blo[half * 2 + 1][1] = r2[3];
            }
            #pragma unroll
            for (int mt = 0; mt < 2; mt++)
                #pragma unroll
                for (int nt = 0; nt < 4; nt++) {
                    mma_bf16(acc[mt][nt], ahi[mt], bhi[nt]);
                    mma_bf16(acc[mt][nt], ahi[mt], blo[nt]);
                    mma_bf16(acc[mt][nt], alo[mt], bhi[nt]);
                }
        }
    };

    int nch = K >> 5;
    load_chunk(0, 0);
    cp_commit();
    for (int c = 0; c < nch; c++) {
        if (c + 1 < nch) {
            load_chunk(c + 1, (c + 1) & 1);
            cp_commit();
            cp_wait<1>();
        } else {
            cp_wait<0>();
        }
        __syncthreads();
        compute(c & 1);
        __syncthreads();
    }

    // ---- epilogue: store C + fused attention logits ----
    int lq = lane & 3;       // quad col selector
    int lr = lane >> 2;      // row within 8
    int head = (colBase + wn * 32) >> 6;   // all cols of this warp lie in one head
    #pragma unroll
    for (int mt = 0; mt < 2; mt++) {
        int r0 = rowBase + wm * 32 + mt * 16 + lr;
        float ss0 = 0.f, sd0 = 0.f, ss1 = 0.f, sd1 = 0.f;
        #pragma unroll
        for (int nt = 0; nt < 4; nt++) {
            int col = colBase + wn * 32 + nt * 8 + lq * 2;
            if (r0 < M)
                *(float2*)(Cm + (size_t)r0 * Nc + col) =
                    make_float2(acc[mt][nt][0], acc[mt][nt][1]);
            if (r0 + 8 < M)
                *(float2*)(Cm + (size_t)(r0 + 8) * Nc + col) =
                    make_float2(acc[mt][nt][2], acc[mt][nt][3]);
            float as0 = a_src[col], as1v = a_src[col + 1];
            float ad0 = a_dst[col], ad1v = a_dst[col + 1];
            ss0 += acc[mt][nt][0] * as0 + acc[mt][nt][1] * as1v;
            sd0 += acc[mt][nt][0] * ad0 + acc[mt][nt][1] * ad1v;
            ss1 += acc[mt][nt][2] * as0 + acc[mt][nt][3] * as1v;
            sd1 += acc[mt][nt][2] * ad0 + acc[mt][nt][3] * ad1v;
        }
        #pragma unroll
        for (int o = 1; o < 4; o <<= 1) {
            ss0 += __shfl_xor_sync(0xffffffffu, ss0, o);
            sd0 += __shfl_xor_sync(0xffffffffu, sd0, o);
            ss1 += __shfl_xor_sync(0xffffffffu, ss1, o);
            sd1 += __shfl_xor_sync(0xffffffffu, sd1, o);
        }
        if (lq == 0) {
            if (r0 < M) {
                atomicAdd(&g_als[r0 * HEADS + head], ss0);
                atomicAdd(&g_ald[r0 * HEADS + head], sd0);
            }
            if (r0 + 8 < M) {
                atomicAdd(&g_als[(r0 + 8) * HEADS + head], ss1);
                atomicAdd(&g_ald[(r0 + 8) * HEADS + head], sd1);
            }
        }
    }
}

// ---------------- GAT aggregation (warp per dst) ----------------
// TO_BF16: write bf16 hi/lo (next GEMM input) instead of fp32.
template <int HEADS, bool DOELU, bool TO_BF16>
__global__ void __launch_bounds__(256) aggregate_k(const float* __restrict__ hlin,
                                                   const float* __restrict__ bias,
                                                   float* __restrict__ hout,
                                                   float* __restrict__ att) {
    int wid = (blockIdx.x * blockDim.x + threadIdx.x) >> 5;
    int lane = threadIdx.x & 31;
    if (wid >= NN) return;
    int n = wid;
    int st = g_rowptr[n], en = g_rowptr[n + 1];

    float ald[HEADS];
    if (HEADS == 4) {
        float4 v = ((const float4*)g_ald)[n];
        ald[0] = v.x; ald[1] = v.y; ald[2] = v.z; ald[3] = v.w;
    } else {
        ald[0] = g_ald[n];
    }

    float m[HEADS];
    #pragma unroll
    for (int h = 0; h < HEADS; h++) m[h] = -1e30f;

    for (int i = st + lane; i < en; i += 32) {
        int s = g_esrc[i];
        if (HEADS == 4) {
            float4 av = ((const float4*)g_als)[s];
            m[0] = fmaxf(m[0], lrelu(av.x + ald[0]));
            m[1] = fmaxf(m[1], lrelu(av.y + ald[1]));
            m[2] = fmaxf(m[2], lrelu(av.z + ald[2]));
            m[3] = fmaxf(m[3], lrelu(av.w + ald[3]));
        } else {
            m[0] = fmaxf(m[0], lrelu(g_als[s] + ald[0]));
        }
    }
    #pragma unroll
    for (int h = 0; h < HEADS; h++)
        #pragma unroll
        for (int off = 16; off; off >>= 1)
            m[h] = fmaxf(m[h], __shfl_xor_sync(0xffffffffu, m[h], off));

    float ssum[HEADS];
    #pragma unroll
    for (int h = 0; h < HEADS; h++) ssum[h] = 0.f;

    if (HEADS == 4) {
        bool lo = lane < 16;
        float4 a0 = make_float4(0.f, 0.f, 0.f, 0.f), a1 = a0;
        for (int i = st; i < en; i++) {
            int s = g_esrc[i];
            float4 av = ((const float4*)g_als)[s];
            float ex0 = __expf(lrelu(av.x + ald[0]) - m[0]);
            float ex1 = __expf(lrelu(av.y + ald[1]) - m[1]);
            float ex2 = __expf(lrelu(av.z + ald[2]) - m[2]);
            float ex3 = __expf(lrelu(av.w + ald[3]) - m[3]);
            ssum[0] += ex0; ssum[1] += ex1; ssum[2] += ex2; ssum[3] += ex3;
            const float4* h4 = (const float4*)(hlin + (size_t)s * 256);
            float4 v0 = h4[lane], v1 = h4[32 + lane];
            float e01 = lo ? ex0 : ex1;
            float e23 = lo ? ex2 : ex3;
            a0.x += e01 * v0.x; a0.y += e01 * v0.y; a0.z += e01 * v0.z; a0.w += e01 * v0.w;
            a1.x += e23 * v1.x; a1.y += e23 * v1.y; a1.z += e23 * v1.z; a1.w += e23 * v1.w;
        }
        float s01 = lo ? ssum[0] : ssum[1];
        float s23 = lo ? ssum[2] : ssum[3];
        const float4* b4 = (const float4*)bias;
        float4 bb0 = b4[lane], bb1 = b4[32 + lane];
        float4 o0, o1;
        o0.x = a0.x / s01 + bb0.x; o0.y = a0.y / s01 + bb0.y;
        o0.z = a0.z / s01 + bb0.z; o0.w = a0.w / s01 + bb0.w;
        o1.x = a1.x / s23 + bb1.x; o1.y = a1.y / s23 + bb1.y;
        o1.z = a1.z / s23 + bb1.z; o1.w = a1.w / s23 + bb1.w;
        if (DOELU) {
            o0.x = o0.x > 0.f ? o0.x : __expf(o0.x) - 1.f;
            o0.y = o0.y > 0.f ? o0.y : __expf(o0.y) - 1.f;
            o0.z = o0.z > 0.f ? o0.z : __expf(o0.z) - 1.f;
            o0.w = o0.w > 0.f ? o0.w : __expf(o0.w) - 1.f;
            o1.x = o1.x > 0.f ? o1.x : __expf(o1.x) - 1.f;
            o1.y = o1.y > 0.f ? o1.y : __expf(o1.y) - 1.f;
            o1.z = o1.z > 0.f ? o1.z : __expf(o1.z) - 1.f;
            o1.w = o1.w > 0.f ? o1.w : __expf(o1.w) - 1.f;
        }
        if (TO_BF16) {
            unsigned short h0[4], l0[4], h1[4], l1[4];
            bf16_split(o0.x, h0[0], l0[0]); bf16_split(o0.y, h0[1], l0[1]);
            bf16_split(o0.z, h0[2], l0[2]); bf16_split(o0.w, h0[3], l0[3]);
            bf16_split(o1.x, h1[0], l1[0]); bf16_split(o1.y, h1[1], l1[1]);
            bf16_split(o1.z, h1[2], l1[2]); bf16_split(o1.w, h1[3], l1[3]);
            uint2* dh0 = (uint2*)(g_Ahi + (size_t)n * 256 + lane * 4);
            uint2* dl0 = (uint2*)(g_Alo + (size_t)n * 256 + lane * 4);
            uint2* dh1 = (uint2*)(g_Ahi + (size_t)n * 256 + 128 + lane * 4);
            uint2* dl1 = (uint2*)(g_Alo + (size_t)n * 256 + 128 + lane * 4);
            *dh0 = make_uint2((uint32_t)h0[0] | ((uint32_t)h0[1] << 16),
                              (uint32_t)h0[2] | ((uint32_t)h0[3] << 16));
            *dl0 = make_uint2((uint32_t)l0[0] | ((uint32_t)l0[1] << 16),
                              (uint32_t)l0[2] | ((uint32_t)l0[3] << 16));
            *dh1 = make_uint2((uint32_t)h1[0] | ((uint32_t)h1[1] << 16),
                              (uint32_t)h1[2] | ((uint32_t)h1[3] << 16));
            *dl1 = make_uint2((uint32_t)l1[0] | ((uint32_t)l1[1] << 16),
                              (uint32_t)l1[2] | ((uint32_t)l1[3] << 16));
        } else {
            float4* ho = (float4*)(hout + (size_t)n * 256);
            ho[lane] = o0;
            ho[32 + lane] = o1;
        }
    } else {
        float2 a = make_float2(0.f, 0.f);
        for (int i = st; i < en; i++) {
            int s = g_esrc[i];
            float ex = __expf(lrelu(g_als[s] + ald[0]) - m[0]);
            ssum[0] += ex;
            const float2* h2 = (const float2*)(hlin + (size_t)s * 64);
            float2 v = h2[lane];
            a.x += ex * v.x;
            a.y += ex * v.y;
        }
        const float2* b2 = (const float2*)bias;
        float2 bb = b2[lane];
        float2 o;
        o.x = a.x / ssum[0] + bb.x;
        o.y = a.y / ssum[0] + bb.y;
        if (DOELU) {
            o.x = o.x > 0.f ? o.x : __expf(o.x) - 1.f;
            o.y = o.y > 0.f ? o.y : __expf(o.y) - 1.f;
        }
        ((float2*)(hout + (size_t)n * 64))[lane] = o;
    }

    for (int i = st + lane; i < en; i += 32) {
        int s = g_esrc[i];
        long long id = g_eid[i];
        if (HEADS == 4) {
            float4 av = ((const float4*)g_als)[s];
            att[id * 4 + 0] = __expf(lrelu(av.x + ald[0]) - m[0]) / ssum[0];
            att[id * 4 + 1] = __expf(lrelu(av.y + ald[1]) - m[1]) / ssum[1];
            att[id * 4 + 2] = __expf(lrelu(av.z + ald[2]) - m[2]) / ssum[2];
            att[id * 4 + 3] = __expf(lrelu(av.w + ald[3]) - m[3]) / ssum[3];
        } else {
            att[id] = __expf(lrelu(g_als[s] + ald[0]) - m[0]) / ssum[0];
        }
    }
}

// ---------------- global mean pool (sum + count) ----------------
__global__ void pool_k(const void* batch, const float* __restrict__ h3) {
    long long t = (long long)blockIdx.x * blockDim.x + threadIdx.x;
    if (t >= (long long)NN * DD) return;
    int n = (int)(t >> 6);
    int d = (int)(t & 63);
    int g = ld_idx(batch, n, g_is64_b);
    atomicAdd(&g_pool[g * DD + d], h3[t]);
    if (d == 0) atomicAdd(&g_cnt[g], 1.f);
}

// ---------------- classifier ----------------
__global__ void classifier_k(const float* __restrict__ Wc1, const float* __restrict__ bc1,
                             const float* __restrict__ Wc2, const float* __restrict__ bc2,
                             float* __restrict__ out) {
    __shared__ float hid[GG][33];
    int t = threadIdx.x;
    for (int idx = t; idx < GG * 32; idx += blockDim.x) {
        int g = idx >> 5, j = idx & 31;
        float inv = 1.f / fmaxf(g_cnt[g], 1.f);
        float s = bc1[j];
        #pragma unroll
        for (int d = 0; d < DD; d++)
            s += (g_pool[g * DD + d] * inv) * Wc1[d * 32 + j];
        hid[g][j] = fmaxf(s, 0.f);
    }
    __syncthreads();
    for (int idx = t; idx < GG * CC; idx += blockDim.x) {
        int g = idx / CC, c = idx % CC;
        float s = bc2[c];
        #pragma unroll
        for (int j = 0; j < 32; j++)
            s += hid[g][j] * Wc2[j * CC + c];
        out[g * CC + c] = s;
    }
}

// ---------------- launch ----------------
extern "C" void kernel_launch(void* const* d_in, const int* in_sizes, int n_in,
                              void* d_out, int out_size) {
    const float* x   = (const float*)d_in[0];
    const void*  ei  = d_in[1];
    const void*  bat = d_in[2];
    const float* W1  = (const float*)d_in[3];
    const float* as1 = (const float*)d_in[4];
    const float* ad1 = (const float*)d_in[5];
    const float* b1  = (const float*)d_in[6];
    const float* W2  = (const float*)d_in[7];
    const float* as2 = (const float*)d_in[8];
    const float* ad2 = (const float*)d_in[9];
    const float* b2  = (const float*)d_in[10];
    const float* W3  = (const float*)d_in[11];
    const float* as3 = (const float*)d_in[12];
    const float* ad3 = (const float*)d_in[13];
    const float* b3  = (const float*)d_in[14];
    const float* Wc1 = (const float*)d_in[15];
    const float* bc1 = (const float*)d_in[16];
    const float* Wc2 = (const float*)d_in[17];
    const float* bc2 = (const float*)d_in[18];

    float* out  = (float*)d_out;
    float* att1 = out + GG * CC;
    float* att2 = att1 + (size_t)ETOT * 4;
    float* att3 = att2 + (size_t)ETOT * 4;

    float *bufA, *bufB;
    cudaGetSymbolAddress((void**)&bufA, g_bufA);
    cudaGetSymbolAddress((void**)&bufB, g_bufB);
    __nv_bfloat16 *Ahi, *Alo, *Whi, *Wlo;
    cudaGetSymbolAddress((void**)&Ahi, g_Ahi);
    cudaGetSymbolAddress((void**)&Alo, g_Alo);
    cudaGetSymbolAddress((void**)&Whi, g_Whi);
    cudaGetSymbolAddress((void**)&Wlo, g_Wlo);

    const int NB_E = (ETOT + 255) / 256;
    const int NB_N = (NN + 255) / 256;
    const int NB_W = (NN * 32 + 255) / 256;   // one warp per node
    const int MB   = (NN + 127) / 128;        // 391 gemm row-blocks

    const int SMEM128 = 2 * (2 * 128 * 64 + 2 * 128 * 64);  // 65536
    const int SMEM64  = 2 * (2 * 128 * 64 + 2 * 64 * 64);   // 49152
    cudaFuncSetAttribute((const void*)gemm_bf16_k<128, 512, 4>,
                         cudaFuncAttributeMaxDynamicSharedMemorySize, SMEM128);
    cudaFuncSetAttribute((const void*)gemm_bf16_k<64, 256, 1>,
                         cudaFuncAttributeMaxDynamicSharedMemorySize, SMEM64);

    zero_k<<<NB_N, 256>>>(ei, bat);
    count_k<<<NB_E, 256>>>(ei);
    scan_k<<<1, 1024>>>();
    scatter_k<<<NB_E, 256>>>(ei);

    // Layer 1: h = x @ W1 -> [N, 256]
    zeroAL_k<<<(NN * 4 + 1023) / 1024, 1024>>>(NN * 4);
    convertX_k<<<(NN * FF / 4 + 255) / 256, 256>>>(x);
    convertW_k<<<(FF * 256 + 255) / 256, 256>>>(W1, FF, 256);
    gemm_bf16_k<128, 512, 4><<<dim3(2, MB), 512, SMEM128>>>(
        Ahi, Alo, Whi, Wlo, bufA, as1, ad1, NN, FF, 256);
    aggregate_k<4, true, true><<<NB_W, 256>>>(bufA, b1, bufB, att1);

    // Layer 2
    zeroAL_k<<<(NN * 4 + 1023) / 1024, 1024>>>(NN * 4);
    convertW_k<<<(256 * 256 + 255) / 256, 256>>>(W2, 256, 256);
    gemm_bf16_k<128, 512, 4><<<dim3(2, MB), 512, SMEM128>>>(
        Ahi, Alo, Whi, Wlo, bufA, as2, ad2, NN, 256, 256);
    aggregate_k<4, true, true><<<NB_W, 256>>>(bufA, b2, bufB, att2);

    // Layer 3: heads=1, D=64, no ELU
    zeroAL_k<<<(NN + 1023) / 1024, 1024>>>(NN);
    convertW_k<<<(256 * 64 + 255) / 256, 256>>>(W3, 256, 64);
    gemm_bf16_k<64, 256, 1><<<dim3(1, MB), 256, SMEM64>>>(
        Ahi, Alo, Whi, Wlo, bufA, as3, ad3, NN, 256, 64);
    aggregate_k<1, false, false><<<NB_W, 256>>>(bufA, b3, bufB, att3);

    // Pool + classify
    pool_k<<<(int)(((long long)NN * DD + 255) / 256), 256>>>(bat, bufB);
    classifier_k<<<1, 256>>>(Wc1, bc1, Wc2, bc2, out);
}

// round 7
// speedup vs baseline: 1.6382x; 1.0426x over previous
#include <cuda_runtime.h>
#include <cuda_bf16.h>
#include <cstdint>
#include <stdint.h>
#include <math.h>

// Problem constants
#define NN 50000
#define EE 800000
#define ETOT (EE + NN)   // 850000 (edges + self loops)
#define FF 128
#define DD 64
#define GG 32
#define CC 3

// ---------------- device scratch ----------------
__device__ float g_bufA[(size_t)NN * 256];            // GEMM output (fp32)
__device__ float g_scr[(size_t)NN * 256];             // ex scratch (>= ETOT*4 floats)
__device__ __nv_bfloat16 g_Ahi[(size_t)NN * 256];     // GEMM A input hi
__device__ __nv_bfloat16 g_Alo[(size_t)NN * 256];     // GEMM A input lo
__device__ __nv_bfloat16 g_W1hi[FF * 256],  g_W1lo[FF * 256];
__device__ __nv_bfloat16 g_W2hi[256 * 256], g_W2lo[256 * 256];
__device__ __nv_bfloat16 g_W3hi[64 * 256],  g_W3lo[64 * 256];
__device__ float g_als1[NN * 4], g_ald1[NN * 4];
__device__ float g_als2[NN * 4], g_ald2[NN * 4];
__device__ float g_als3[NN],     g_ald3[NN];
__device__ int   g_rowptr[NN + 1];
__device__ int   g_cursor[NN];
__device__ int   g_esrc[ETOT];
__device__ int   g_eid[ETOT];
__device__ float g_pool[GG * DD];
__device__ int   g_is64_ei;
__device__ int   g_is64_b;

// ---------------- helpers ----------------
__device__ __forceinline__ float lrelu(float x) { return x > 0.f ? x : 0.2f * x; }

__device__ __forceinline__ int ld_idx(const void* p, long long i, int is64) {
    if (is64) return ((const int*)p)[2 * i];
    return ((const int*)p)[i];
}

__device__ __forceinline__ uint32_t smem_to_u32(const void* smem_ptr) {
    uint32_t addr;
    asm("{ .reg .u64 tmp; cvta.to.shared.u64 tmp, %1; cvt.u32.u64 %0, tmp; }"
        : "=r"(addr) : "l"(smem_ptr));
    return addr;
}

__device__ __forceinline__ void cp_async16(uint32_t dst, const void* src, int sz) {
    asm volatile("cp.async.ca.shared.global [%0], [%1], 16, %2;"
                 :: "r"(dst), "l"(src), "r"(sz));
}
__device__ __forceinline__ void cp_commit() {
    asm volatile("cp.async.commit_group;" ::: "memory");
}
template <int N>
__device__ __forceinline__ void cp_wait() {
    asm volatile("cp.async.wait_group %0;" :: "n"(N) : "memory");
}

__device__ __forceinline__ void ldsm_x4(uint32_t* r, uint32_t a) {
    asm volatile("ldmatrix.sync.aligned.m8n8.x4.shared.b16 {%0,%1,%2,%3}, [%4];"
                 : "=r"(r[0]), "=r"(r[1]), "=r"(r[2]), "=r"(r[3]) : "r"(a));
}

__device__ __forceinline__ void mma_bf16(float* d, const uint32_t* a, const uint32_t* b) {
    asm volatile(
        "mma.sync.aligned.m16n8k16.row.col.f32.bf16.bf16.f32 "
        "{%0,%1,%2,%3},{%4,%5,%6,%7},{%8,%9},{%0,%1,%2,%3};"
        : "+f"(d[0]), "+f"(d[1]), "+f"(d[2]), "+f"(d[3])
        : "r"(a[0]), "r"(a[1]), "r"(a[2]), "r"(a[3]), "r"(b[0]), "r"(b[1]));
}

__device__ __forceinline__ void bf16_split(float v, unsigned short& h, unsigned short& l) {
    __nv_bfloat16 hb = __float2bfloat16_rn(v);
    h = __bfloat16_as_ushort(hb);
    l = __bfloat16_as_ushort(__float2bfloat16_rn(v - __bfloat162float(hb)));
}

// ---------------- prep: detect + zero + convert X, W1, W2, W3 ----------------
#define BX  6250            // convertX blocks (NN*FF/4 / 256 exactly)
#define BW1 128             // 128*256/256
#define BW2 256             // 256*256/256
#define BW3 64              // 64*256/256
#define NZ  (NN + GG * DD + NN * 4 + NN)
#define BZ  ((NZ + 255) / 256)
#define PREP_BLOCKS (BX + BW1 + BW2 + BW3 + BZ)

__global__ void prep_k(const float* __restrict__ x, const float* __restrict__ W1,
                       const float* __restrict__ W2, const float* __restrict__ W3,
                       const void* ei, const void* batch) {
    int b = blockIdx.x, t = threadIdx.x;
    if (b == 0 && t == 0) {
        const int* p = (const int*)ei;
        bool z = true;
        #pragma unroll
        for (int j = 0; j < 16; j++) z = z && (p[2 * j + 1] == 0);
        g_is64_ei = z ? 1 : 0;
        const int* q = (const int*)batch;
        bool zb = true;
        #pragma unroll
        for (int j = 0; j < 16; j++) zb = zb && (q[NN - 1 - 2 * j] == 0);
        g_is64_b = zb ? 1 : 0;
    }
    if (b < BX) {
        size_t i4 = (size_t)b * 256 + t;
        float4 v = ((const float4*)x)[i4];
        unsigned short h[4], l[4];
        bf16_split(v.x, h[0], l[0]);
        bf16_split(v.y, h[1], l[1]);
        bf16_split(v.z, h[2], l[2]);
        bf16_split(v.w, h[3], l[3]);
        ((uint2*)g_Ahi)[i4] = make_uint2((uint32_t)h[0] | ((uint32_t)h[1] << 16),
                                         (uint32_t)h[2] | ((uint32_t)h[3] << 16));
        ((uint2*)g_Alo)[i4] = make_uint2((uint32_t)l[0] | ((uint32_t)l[1] << 16),
                                         (uint32_t)l[2] | ((uint32_t)l[3] << 16));
    } else if (b < BX + BW1) {
        int idx = (b - BX) * 256 + t;           // [N=256][K=128]
        int n = idx >> 7, k = idx & 127;
        unsigned short h, l;
        bf16_split(W1[(size_t)k * 256 + n], h, l);
        g_W1hi[idx] = __ushort_as_bfloat16(h);
        g_W1lo[idx] = __ushort_as_bfloat16(l);
    } else if (b < BX + BW1 + BW2) {
        int idx = (b - BX - BW1) * 256 + t;     // [N=256][K=256]
        int n = idx >> 8, k = idx & 255;
        unsigned short h, l;
        bf16_split(W2[(size_t)k * 256 + n], h, l);
        g_W2hi[idx] = __ushort_as_bfloat16(h);
        g_W2lo[idx] = __ushort_as_bfloat16(l);
    } else if (b < BX + BW1 + BW2 + BW3) {
        int idx = (b - BX - BW1 - BW2) * 256 + t;  // [N=64][K=256]
        int n = idx >> 8, k = idx & 255;
        unsigned short h, l;
        bf16_split(W3[(size_t)k * 64 + n], h, l);
        g_W3hi[idx] = __ushort_as_bfloat16(h);
        g_W3lo[idx] = __ushort_as_bfloat16(l);
    } else {
        int zi = (b - BX - BW1 - BW2 - BW3) * 256 + t;
        if (zi < NN) { g_cursor[zi] = 0; return; }
        zi -= NN;
        if (zi < GG * DD) { g_pool[zi] = 0.f; return; }
        zi -= GG * DD;
        if (zi < NN * 4) {
            g_als1[zi] = 0.f; g_ald1[zi] = 0.f;
            g_als2[zi] = 0.f; g_ald2[zi] = 0.f;
            return;
        }
        zi -= NN * 4;
        if (zi < NN) { g_als3[zi] = 0.f; g_ald3[zi] = 0.f; }
    }
}

// ---------------- CSR build ----------------
__global__ void count_k(const void* ei) {
    long long e = (long long)blockIdx.x * blockDim.x + threadIdx.x;
    if (e >= ETOT) return;
    int is64 = g_is64_ei;
    int d = (e < EE) ? ld_idx(ei, (long long)EE + e, is64) : (int)(e - EE);
    atomicAdd(&g_cursor[d], 1);
}

__global__ void scan_k() {
    __shared__ int wsum[32];
    const int CH = 49;
    int t = threadIdx.x;
    int base = t * CH;
    int s = 0;
    for (int i = 0; i < CH; i++) {
        int idx = base + i;
        if (idx < NN) s += g_cursor[idx];
    }
    int lane = t & 31, w = t >> 5;
    int v = s;
    #pragma unroll
    for (int o = 1; o < 32; o <<= 1) {
        int u = __shfl_up_sync(0xffffffffu, v, o);
        if (lane >= o) v += u;
    }
    if (lane == 31) wsum[w] = v;
    __syncthreads();
    if (w == 0) {
        int x = wsum[lane];
        #pragma unroll
        for (int o = 1; o < 32; o <<= 1) {
            int u = __shfl_up_sync(0xffffffffu, x, o);
            if (lane >= o) x += u;
        }
        wsum[lane] = x;
    }
    __syncthreads();
    int excl = v - s + (w > 0 ? wsum[w - 1] : 0);
    for (int i = 0; i < CH; i++) {
        int idx = base + i;
        if (idx < NN) {
            int c = g_cursor[idx];
            g_rowptr[idx] = excl;
            g_cursor[idx] = excl;
            excl += c;
        }
    }
    if (t == 1023) g_rowptr[NN] = excl;
}

__global__ void scatter_k(const void* ei) {
    long long e = (long long)blockIdx.x * blockDim.x + threadIdx.x;
    if (e >= ETOT) return;
    int is64 = g_is64_ei;
    int s, d;
    if (e < EE) {
        s = ld_idx(ei, e, is64);
        d = ld_idx(ei, (long long)EE + e, is64);
    } else {
        s = d = (int)(e - EE);
    }
    int pos = atomicAdd(&g_cursor[d], 1);
    g_esrc[pos] = s;
    g_eid[pos]  = (int)e;
}

// ---------------- bf16 3-split mma.sync GEMM + fused attention logits ----------------
template <int N_TILE, int THREADS, int HEADS>
__global__ void __launch_bounds__(THREADS) gemm_bf16_k(
    const __nv_bfloat16* __restrict__ Ahi, const __nv_bfloat16* __restrict__ Alo,
    const __nv_bfloat16* __restrict__ Bhi, const __nv_bfloat16* __restrict__ Blo,
    float* __restrict__ Cm,
    const float* __restrict__ a_src, const float* __restrict__ a_dst,
    float* __restrict__ alsO, float* __restrict__ aldO,
    int M, int K, int Nc) {
    constexpr int ABYTES = 128 * 64;
    constexpr int BBYTES = N_TILE * 64;
    constexpr int STAGE  = 2 * ABYTES + 2 * BBYTES;

    extern __shared__ char sm[];
    uint32_t sbase = smem_to_u32(sm);

    int tid = threadIdx.x;
    int warp = tid >> 5, lane = tid & 31;
    int rowBase = blockIdx.y * 128;
    int colBase = blockIdx.x * N_TILE;
    int wm = warp & 3;
    int wn = warp >> 2;

    float acc[2][4][4];
    #pragma unroll
    for (int i = 0; i < 2; i++)
        #pragma unroll
        for (int j = 0; j < 4; j++)
            #pragma unroll
            for (int q = 0; q < 4; q++) acc[i][j][q] = 0.f;

    auto load_chunk = [&](int c, int s) {
        int k0 = c * 32;
        uint32_t so = sbase + s * STAGE;
        #pragma unroll
        for (int u = tid; u < 512; u += THREADS) {
            int row = u >> 2, q = u & 3;
            uint32_t d = so + row * 64 + ((q ^ ((row >> 1) & 3)) * 16);
            size_t goff = (size_t)(rowBase + row) * K + k0 + q * 8;
            int sz = (rowBase + row < M) ? 16 : 0;
            cp_async16(d, Ahi + goff, sz);
            cp_async16(d + ABYTES, Alo + goff, sz);
        }
        #pragma unroll
        for (int u = tid; u < N_TILE * 4; u += THREADS) {
            int row = u >> 2, q = u & 3;
            uint32_t d = so + 2 * ABYTES + row * 64 + ((q ^ ((row >> 1) & 3)) * 16);
            size_t goff = (size_t)(colBase + row) * K + k0 + q * 8;
            cp_async16(d, Bhi + goff, 16);
            cp_async16(d + BBYTES, Blo + goff, 16);
        }
    };

    auto compute = [&](int s) {
        uint32_t aB = sbase + s * STAGE;
        uint32_t bB = aB + 2 * ABYTES;
        #pragma unroll
        for (int k16 = 0; k16 < 2; k16++) {
            int usel = k16 * 2 + (lane >> 4);
            uint32_t ahi[2][4], alo[2][4];
            #pragma unroll
            for (int mt = 0; mt < 2; mt++) {
                int row = wm * 32 + mt * 16 + (lane & 15);
                uint32_t addr = aB + row * 64 + ((usel ^ ((row >> 1) & 3)) * 16);
                ldsm_x4(ahi[mt], addr);
                ldsm_x4(alo[mt], addr + ABYTES);
            }
            uint32_t bhi[4][2], blo[4][2];
            #pragma unroll
            for (int half = 0; half < 2; half++) {
                int row = wn * 32 + half * 16 + (lane & 15);
                uint32_t addr = bB + row * 64 + ((usel ^ ((row >> 1) & 3)) * 16);
                uint32_t r[4], r2[4];
                ldsm_x4(r, addr);
                ldsm_x4(r2, addr + BBYTES);
                bhi[half * 2 + 0][0] = r[0];  bhi[half * 2 + 0][1] = r[2];
                bhi[half * 2 + 1][0] = r[1];  bhi[half * 2 + 1][1] = r[3];
                blo[half * 2 + 0][0] = r2[0]; blo[half * 2 + 0][1] = r2[2];
                blo[half * 2 + 1][0] = r2[1]; blo[half * 2 + 1][1] = r2[3];
            }
            #pragma unroll
            for (int mt = 0; mt < 2; mt++)
                #pragma unroll
                for (int nt = 0; nt < 4; nt++) {
                    mma_bf16(acc[mt][nt], ahi[mt], bhi[nt]);
                    mma_bf16(acc[mt][nt], ahi[mt], blo[nt]);
                    mma_bf16(acc[mt][nt], alo[mt], bhi[nt]);
                }
        }
    };

    int nch = K >> 5;
    load_chunk(0, 0);
    cp_commit();
    for (int c = 0; c < nch; c++) {
        if (c + 1 < nch) {
            load_chunk(c + 1, (c + 1) & 1);
            cp_commit();
            cp_wait<1>();
        } else {
            cp_wait<0>();
        }
        __syncthreads();
        compute(c & 1);
        __syncthreads();
    }

    // ---- epilogue: store C + fused attention logits ----
    int lq = lane & 3;
    int lr = lane >> 2;
    int head = (colBase + wn * 32) >> 6;
    #pragma unroll
    for (int mt = 0; mt < 2; mt++) {
        int r0 = rowBase + wm * 32 + mt * 16 + lr;
        float ss0 = 0.f, sd0 = 0.f, ss1 = 0.f, sd1 = 0.f;
        #pragma unroll
        for (int nt = 0; nt < 4; nt++) {
            int col = colBase + wn * 32 + nt * 8 + lq * 2;
            if (r0 < M)
                *(float2*)(Cm + (size_t)r0 * Nc + col) =
                    make_float2(acc[mt][nt][0], acc[mt][nt][1]);
            if (r0 + 8 < M)
                *(float2*)(Cm + (size_t)(r0 + 8) * Nc + col) =
                    make_float2(acc[mt][nt][2], acc[mt][nt][3]);
            float as0 = a_src[col], as1v = a_src[col + 1];
            float ad0 = a_dst[col], ad1v = a_dst[col + 1];
            ss0 += acc[mt][nt][0] * as0 + acc[mt][nt][1] * as1v;
            sd0 += acc[mt][nt][0] * ad0 + acc[mt][nt][1] * ad1v;
            ss1 += acc[mt][nt][2] * as0 + acc[mt][nt][3] * as1v;
            sd1 += acc[mt][nt][2] * ad0 + acc[mt][nt][3] * ad1v;
        }
        #pragma unroll
        for (int o = 1; o < 4; o <<= 1) {
            ss0 += __shfl_xor_sync(0xffffffffu, ss0, o);
            sd0 += __shfl_xor_sync(0xffffffffu, sd0, o);
            ss1 += __shfl_xor_sync(0xffffffffu, ss1, o);
            sd1 += __shfl_xor_sync(0xffffffffu, sd1, o);
        }
        if (lq == 0) {
            if (r0 < M) {
                atomicAdd(&alsO[r0 * HEADS + head], ss0);
                atomicAdd(&aldO[r0 * HEADS + head], sd0);
            }
            if (r0 + 8 < M) {
                atomicAdd(&alsO[(r0 + 8) * HEADS + head], ss1);
                atomicAdd(&aldO[(r0 + 8) * HEADS + head], sd1);
            }
        }
    }
}

// ---------------- GAT aggregation (warp per dst; no segment-max; shfl broadcast) ----
// HEADS==4: DOELU + bf16 output into g_Ahi/g_Alo. HEADS==1: fused mean-pool.
template <int HEADS>
__global__ void __launch_bounds__(256) aggregate_k(
    const float* __restrict__ hlin, const float* __restrict__ als,
    const float* __restrict__ ald, const float* __restrict__ bias,
    float* __restrict__ att, const void* batch) {
    int wid = (blockIdx.x * blockDim.x + threadIdx.x) >> 5;
    int lane = threadIdx.x & 31;
    if (wid >= NN) return;
    int n = wid;
    int st = g_rowptr[n], en = g_rowptr[n + 1];

    if (HEADS == 4) {
        float4 ad4 = ((const float4*)ald)[n];
        bool lo = lane < 16;
        float4 accA = make_float4(0.f, 0.f, 0.f, 0.f), accB = accA;
        float s0 = 0.f, s1 = 0.f, s2 = 0.f, s3 = 0.f;

        for (int base = st; base < en; base += 32) {
            int i = base + lane;
            int cnt = min(32, en - base);
            int s = 0;
            float ex0 = 0.f, ex1 = 0.f, ex2 = 0.f, ex3 = 0.f;
            if (i < en) {
                s = g_esrc[i];
                float4 av = ((const float4*)als)[s];
                ex0 = __expf(lrelu(av.x + ad4.x));
                ex1 = __expf(lrelu(av.y + ad4.y));
                ex2 = __expf(lrelu(av.z + ad4.z));
                ex3 = __expf(lrelu(av.w + ad4.w));
                s0 += ex0; s1 += ex1; s2 += ex2; s3 += ex3;
                ((float4*)g_scr)[i] = make_float4(ex0, ex1, ex2, ex3);
            }
            for (int e = 0; e < cnt; e++) {
                int se = __shfl_sync(0xffffffffu, s, e);
                float e0 = __shfl_sync(0xffffffffu, ex0, e);
                float e1 = __shfl_sync(0xffffffffu, ex1, e);
                float e2 = __shfl_sync(0xffffffffu, ex2, e);
                float e3 = __shfl_sync(0xffffffffu, ex3, e);
                const float4* h4 = (const float4*)(hlin + (size_t)se * 256);
                float4 v0 = h4[lane], v1 = h4[32 + lane];
                float eA = lo ? e0 : e1;
                float eB = lo ? e2 : e3;
                accA.x += eA * v0.x; accA.y += eA * v0.y;
                accA.z += eA * v0.z; accA.w += eA * v0.w;
                accB.x += eB * v1.x; accB.y += eB * v1.y;
                accB.z += eB * v1.z; accB.w += eB * v1.w;
            }
        }
        #pragma unroll
        for (int o = 16; o; o >>= 1) {
            s0 += __shfl_xor_sync(0xffffffffu, s0, o);
            s1 += __shfl_xor_sync(0xffffffffu, s1, o);
            s2 += __shfl_xor_sync(0xffffffffu, s2, o);
            s3 += __shfl_xor_sync(0xffffffffu, s3, o);
        }
        float invA = 1.f / (lane < 16 ? s0 : s1);
        float invB = 1.f / (lane < 16 ? s2 : s3);
        const float4* b4 = (const float4*)bias;
        float4 bb0 = b4[lane], bb1 = b4[32 + lane];
        float4 o0, o1;
        o0.x = accA.x * invA + bb0.x; o0.y = accA.y * invA + bb0.y;
        o0.z = accA.z * invA + bb0.z; o0.w = accA.w * invA + bb0.w;
        o1.x = accB.x * invB + bb1.x; o1.y = accB.y * invB + bb1.y;
        o1.z = accB.z * invB + bb1.z; o1.w = accB.w * invB + bb1.w;
        // ELU
        o0.x = o0.x > 0.f ? o0.x : __expf(o0.x) - 1.f;
        o0.y = o0.y > 0.f ? o0.y : __expf(o0.y) - 1.f;
        o0.z = o0.z > 0.f ? o0.z : __expf(o0.z) - 1.f;
        o0.w = o0.w > 0.f ? o0.w : __expf(o0.w) - 1.f;
        o1.x = o1.x > 0.f ? o1.x : __expf(o1.x) - 1.f;
        o1.y = o1.y > 0.f ? o1.y : __expf(o1.y) - 1.f;
        o1.z = o1.z > 0.f ? o1.z : __expf(o1.z) - 1.f;
        o1.w = o1.w > 0.f ? o1.w : __expf(o1.w) - 1.f;
        // bf16 hi/lo output (next GEMM input)
        unsigned short h0[4], l0[4], h1[4], l1[4];
        bf16_split(o0.x, h0[0], l0[0]); bf16_split(o0.y, h0[1], l0[1]);
        bf16_split(o0.z, h0[2], l0[2]); bf16_split(o0.w, h0[3], l0[3]);
        bf16_split(o1.x, h1[0], l1[0]); bf16_split(o1.y, h1[1], l1[1]);
        bf16_split(o1.z, h1[2], l1[2]); bf16_split(o1.w, h1[3], l1[3]);
        *(uint2*)(g_Ahi + (size_t)n * 256 + lane * 4) =
            make_uint2((uint32_t)h0[0] | ((uint32_t)h0[1] << 16),
                       (uint32_t)h0[2] | ((uint32_t)h0[3] << 16));
        *(uint2*)(g_Alo + (size_t)n * 256 + lane * 4) =
            make_uint2((uint32_t)l0[0] | ((uint32_t)l0[1] << 16),
                       (uint32_t)l0[2] | ((uint32_t)l0[3] << 16));
        *(uint2*)(g_Ahi + (size_t)n * 256 + 128 + lane * 4) =
            make_uint2((uint32_t)h1[0] | ((uint32_t)h1[1] << 16),
                       (uint32_t)h1[2] | ((uint32_t)h1[3] << 16));
        *(uint2*)(g_Alo + (size_t)n * 256 + 128 + lane * 4) =
            make_uint2((uint32_t)l1[0] | ((uint32_t)l1[1] << 16),
                       (uint32_t)l1[2] | ((uint32_t)l1[3] << 16));
        // alpha writeback
        float4 inv4 = make_float4(1.f / s0, 1.f / s1, 1.f / s2, 1.f / s3);
        for (int i = st + lane; i < en; i += 32) {
            float4 exv = ((const float4*)g_scr)[i];
            int id = g_eid[i];
            ((float4*)att)[id] = make_float4(exv.x * inv4.x, exv.y * inv4.y,
                                             exv.z * inv4.z, exv.w * inv4.w);
        }
    } else {
        float ad = ald[n];
        float2 acc = make_float2(0.f, 0.f);
        float ssum = 0.f;
        for (int base = st; base < en; base += 32) {
            int i = base + lane;
            int cnt = min(32, en - base);
            int s = 0;
            float ex = 0.f;
            if (i < en) {
                s = g_esrc[i];
                ex = __expf(lrelu(als[s] + ad));
                ssum += ex;
                g_scr[i] = ex;
            }
            for (int e = 0; e < cnt; e++) {
                int se = __shfl_sync(0xffffffffu, s, e);
                float e0 = __shfl_sync(0xffffffffu, ex, e);
                float2 v = ((const float2*)(hlin + (size_t)se * 64))[lane];
                acc.x += e0 * v.x;
                acc.y += e0 * v.y;
            }
        }
        #pragma unroll
        for (int o = 16; o; o >>= 1)
            ssum += __shfl_xor_sync(0xffffffffu, ssum, o);
        float inv = 1.f / ssum;
        float2 bb = ((const float2*)bias)[lane];
        float2 o;
        o.x = acc.x * inv + bb.x;
        o.y = acc.y * inv + bb.y;
        // fused mean-pool accumulation
        int g = ld_idx(batch, n, g_is64_b);
        atomicAdd(&g_pool[g * DD + lane * 2 + 0], o.x);
        atomicAdd(&g_pool[g * DD + lane * 2 + 1], o.y);
        // alpha writeback
        for (int i = st + lane; i < en; i += 32) {
            float exv = g_scr[i];
            int id = g_eid[i];
            att[id] = exv * inv;
        }
    }
}

// ---------------- classifier (computes per-graph counts via binary search) --------
__global__ void classifier_k(const float* __restrict__ Wc1, const float* __restrict__ bc1,
                             const float* __restrict__ Wc2, const float* __restrict__ bc2,
                             float* __restrict__ out, const void* batch) {
    __shared__ int bnd[GG + 1];
    __shared__ float hid[GG][33];
    int t = threadIdx.x;
    if (t <= GG) {
        int lo = 0, hi = NN;
        while (lo < hi) {
            int mid = (lo + hi) >> 1;
            if (ld_idx(batch, mid, g_is64_b) < t) lo = mid + 1;
            else hi = mid;
        }
        bnd[t] = lo;
    }
    __syncthreads();
    for (int idx = t; idx < GG * 32; idx += blockDim.x) {
        int g = idx >> 5, j = idx & 31;
        float cnt = (float)(bnd[g + 1] - bnd[g]);
        float inv = 1.f / fmaxf(cnt, 1.f);
        float s = bc1[j];
        #pragma unroll
        for (int d = 0; d < DD; d++)
            s += (g_pool[g * DD + d] * inv) * Wc1[d * 32 + j];
        hid[g][j] = fmaxf(s, 0.f);
    }
    __syncthreads();
    for (int idx = t; idx < GG * CC; idx += blockDim.x) {
        int g = idx / CC, c = idx % CC;
        float s = bc2[c];
        #pragma unroll
        for (int j = 0; j < 32; j++)
            s += hid[g][j] * Wc2[j * CC + c];
        out[g * CC + c] = s;
    }
}

// ---------------- launch ----------------
extern "C" void kernel_launch(void* const* d_in, const int* in_sizes, int n_in,
                              void* d_out, int out_size) {
    const float* x   = (const float*)d_in[0];
    const void*  ei  = d_in[1];
    const void*  bat = d_in[2];
    const float* W1  = (const float*)d_in[3];
    const float* as1 = (const float*)d_in[4];
    const float* ad1 = (const float*)d_in[5];
    const float* b1  = (const float*)d_in[6];
    const float* W2  = (const float*)d_in[7];
    const float* as2 = (const float*)d_in[8];
    const float* ad2 = (const float*)d_in[9];
    const float* b2  = (const float*)d_in[10];
    const float* W3  = (const float*)d_in[11];
    const float* as3 = (const float*)d_in[12];
    const float* ad3 = (const float*)d_in[13];
    const float* b3  = (const float*)d_in[14];
    const float* Wc1 = (const float*)d_in[15];
    const float* bc1 = (const float*)d_in[16];
    const float* Wc2 = (const float*)d_in[17];
    const float* bc2 = (const float*)d_in[18];

    float* out  = (float*)d_out;
    float* att1 = out + GG * CC;
    float* att2 = att1 + (size_t)ETOT * 4;
    float* att3 = att2 + (size_t)ETOT * 4;

    float* bufA;
    cudaGetSymbolAddress((void**)&bufA, g_bufA);
    __nv_bfloat16 *Ahi, *Alo, *W1h, *W1l, *W2h, *W2l, *W3h, *W3l;
    cudaGetSymbolAddress((void**)&Ahi, g_Ahi);
    cudaGetSymbolAddress((void**)&Alo, g_Alo);
    cudaGetSymbolAddress((void**)&W1h, g_W1hi);
    cudaGetSymbolAddress((void**)&W1l, g_W1lo);
    cudaGetSymbolAddress((void**)&W2h, g_W2hi);
    cudaGetSymbolAddress((void**)&W2l, g_W2lo);
    cudaGetSymbolAddress((void**)&W3h, g_W3hi);
    cudaGetSymbolAddress((void**)&W3l, g_W3lo);
    float *als1, *ald1, *als2, *ald2, *als3, *ald3;
    cudaGetSymbolAddress((void**)&als1, g_als1);
    cudaGetSymbolAddress((void**)&ald1, g_ald1);
    cudaGetSymbolAddress((void**)&als2, g_als2);
    cudaGetSymbolAddress((void**)&ald2, g_ald2);
    cudaGetSymbolAddress((void**)&als3, g_als3);
    cudaGetSymbolAddress((void**)&ald3, g_ald3);

    const int NB_E = (ETOT + 255) / 256;
    const int NB_W = (NN * 32 + 255) / 256;   // one warp per node
    const int MB   = (NN + 127) / 128;

    const int SMEM128 = 2 * (2 * 128 * 64 + 2 * 128 * 64);  // 65536
    const int SMEM64  = 2 * (2 * 128 * 64 + 2 * 64 * 64);   // 49152
    cudaFuncSetAttribute((const void*)gemm_bf16_k<128, 512, 4>,
                         cudaFuncAttributeMaxDynamicSharedMemorySize, SMEM128);
    cudaFuncSetAttribute((const void*)gemm_bf16_k<64, 256, 1>,
                         cudaFuncAttributeMaxDynamicSharedMemorySize, SMEM64);

    prep_k<<<PREP_BLOCKS, 256>>>(x, W1, W2, W3, ei, bat);
    count_k<<<NB_E, 256>>>(ei);
    scan_k<<<1, 1024>>>();
    scatter_k<<<NB_E, 256>>>(ei);

    // Layer 1
    gemm_bf16_k<128, 512, 4><<<dim3(2, MB), 512, SMEM128>>>(
        Ahi, Alo, W1h, W1l, bufA, as1, ad1, als1, ald1, NN, FF, 256);
    aggregate_k<4><<<NB_W, 256>>>(bufA, als1, ald1, b1, att1, bat);

    // Layer 2
    gemm_bf16_k<128, 512, 4><<<dim3(2, MB), 512, SMEM128>>>(
        Ahi, Alo, W2h, W2l, bufA, as2, ad2, als2, ald2, NN, 256, 256);
    aggregate_k<4><<<NB_W, 256>>>(bufA, als2, ald2, b2, att2, bat);

    // Layer 3
    gemm_bf16_k<64, 256, 1><<<dim3(1, MB), 256, SMEM64>>>(
        Ahi, Alo, W3h, W3l, bufA, as3, ad3, als3, ald3, NN, 256, 64);
    aggregate_k<1><<<NB_W, 256>>>(bufA, als3, ald3, b3, att3, bat);

    classifier_k<<<1, 256>>>(Wc1, bc1, Wc2, bc2, out, bat);
}

// round 8
// speedup vs baseline: 1.6585x; 1.0124x over previous
#include <cuda_runtime.h>
#include <cuda_bf16.h>
#include <cstdint>
#include <stdint.h>
#include <math.h>

// Problem constants
#define NN 50000
#define EE 800000
#define ETOT (EE + NN)   // 850000 (edges + self loops)
#define FF 128
#define DD 64
#define GG 32
#define CC 3

// ---------------- device scratch ----------------
__device__ float g_bufA[(size_t)NN * 256];            // GEMM output (fp32)
__device__ float g_scr[(size_t)NN * 256];             // ex scratch (>= ETOT*4 floats)
__device__ __nv_bfloat16 g_Ahi[(size_t)NN * 256];     // GEMM A input hi
__device__ __nv_bfloat16 g_Alo[(size_t)NN * 256];     // GEMM A input lo
__device__ __nv_bfloat16 g_W1hi[FF * 256],  g_W1lo[FF * 256];
__device__ __nv_bfloat16 g_W2hi[256 * 256], g_W2lo[256 * 256];
__device__ __nv_bfloat16 g_W3hi[64 * 256],  g_W3lo[64 * 256];
__device__ float g_als1[NN * 4], g_ald1[NN * 4];
__device__ float g_als2[NN * 4], g_ald2[NN * 4];
__device__ float g_als3[NN],     g_ald3[NN];
__device__ int   g_rowptr[NN + 1];
__device__ int   g_cursor[NN];
__device__ int   g_esrc[ETOT];
__device__ int   g_eid[ETOT];
__device__ float g_pool[GG * DD];
__device__ int   g_is64_ei;
__device__ int   g_is64_b;

// ---------------- helpers ----------------
__device__ __forceinline__ float lrelu(float x) { return x > 0.f ? x : 0.2f * x; }

__device__ __forceinline__ int ld_idx(const void* p, long long i, int is64) {
    if (is64) return ((const int*)p)[2 * i];
    return ((const int*)p)[i];
}

__device__ __forceinline__ uint32_t smem_to_u32(const void* smem_ptr) {
    uint32_t addr;
    asm("{ .reg .u64 tmp; cvta.to.shared.u64 tmp, %1; cvt.u32.u64 %0, tmp; }"
        : "=r"(addr) : "l"(smem_ptr));
    return addr;
}

__device__ __forceinline__ void cp_async16(uint32_t dst, const void* src, int sz) {
    asm volatile("cp.async.cg.shared.global [%0], [%1], 16, %2;"
                 :: "r"(dst), "l"(src), "r"(sz));
}
__device__ __forceinline__ void cp_commit() {
    asm volatile("cp.async.commit_group;" ::: "memory");
}
template <int N>
__device__ __forceinline__ void cp_wait() {
    asm volatile("cp.async.wait_group %0;" :: "n"(N) : "memory");
}

__device__ __forceinline__ void ldsm_x4(uint32_t* r, uint32_t a) {
    asm volatile("ldmatrix.sync.aligned.m8n8.x4.shared.b16 {%0,%1,%2,%3}, [%4];"
                 : "=r"(r[0]), "=r"(r[1]), "=r"(r[2]), "=r"(r[3]) : "r"(a));
}

__device__ __forceinline__ void mma_bf16(float* d, const uint32_t* a, const uint32_t* b) {
    asm volatile(
        "mma.sync.aligned.m16n8k16.row.col.f32.bf16.bf16.f32 "
        "{%0,%1,%2,%3},{%4,%5,%6,%7},{%8,%9},{%0,%1,%2,%3};"
        : "+f"(d[0]), "+f"(d[1]), "+f"(d[2]), "+f"(d[3])
        : "r"(a[0]), "r"(a[1]), "r"(a[2]), "r"(a[3]), "r"(b[0]), "r"(b[1]));
}

__device__ __forceinline__ void bf16_split(float v, unsigned short& h, unsigned short& l) {
    __nv_bfloat16 hb = __float2bfloat16_rn(v);
    h = __bfloat16_as_ushort(hb);
    l = __bfloat16_as_ushort(__float2bfloat16_rn(v - __bfloat162float(hb)));
}

// ---------------- prep: detect + zero + convert X, W1, W2, W3 ----------------
#define BX  6250
#define BW1 128
#define BW2 256
#define BW3 64
#define NZ  (NN + GG * DD + NN * 4 + NN)
#define BZ  ((NZ + 255) / 256)
#define PREP_BLOCKS (BX + BW1 + BW2 + BW3 + BZ)

__global__ void prep_k(const float* __restrict__ x, const float* __restrict__ W1,
                       const float* __restrict__ W2, const float* __restrict__ W3,
                       const void* ei, const void* batch) {
    int b = blockIdx.x, t = threadIdx.x;
    if (b == 0 && t == 0) {
        const int* p = (const int*)ei;
        bool z = true;
        #pragma unroll
        for (int j = 0; j < 16; j++) z = z && (p[2 * j + 1] == 0);
        g_is64_ei = z ? 1 : 0;
        const int* q = (const int*)batch;
        bool zb = true;
        #pragma unroll
        for (int j = 0; j < 16; j++) zb = zb && (q[NN - 1 - 2 * j] == 0);
        g_is64_b = zb ? 1 : 0;
    }
    if (b < BX) {
        size_t i4 = (size_t)b * 256 + t;
        float4 v = ((const float4*)x)[i4];
        unsigned short h[4], l[4];
        bf16_split(v.x, h[0], l[0]);
        bf16_split(v.y, h[1], l[1]);
        bf16_split(v.z, h[2], l[2]);
        bf16_split(v.w, h[3], l[3]);
        ((uint2*)g_Ahi)[i4] = make_uint2((uint32_t)h[0] | ((uint32_t)h[1] << 16),
                                         (uint32_t)h[2] | ((uint32_t)h[3] << 16));
        ((uint2*)g_Alo)[i4] = make_uint2((uint32_t)l[0] | ((uint32_t)l[1] << 16),
                                         (uint32_t)l[2] | ((uint32_t)l[3] << 16));
    } else if (b < BX + BW1) {
        int idx = (b - BX) * 256 + t;           // [N=256][K=128]
        int n = idx >> 7, k = idx & 127;
        unsigned short h, l;
        bf16_split(W1[(size_t)k * 256 + n], h, l);
        g_W1hi[idx] = __ushort_as_bfloat16(h);
        g_W1lo[idx] = __ushort_as_bfloat16(l);
    } else if (b < BX + BW1 + BW2) {
        int idx = (b - BX - BW1) * 256 + t;     // [N=256][K=256]
        int n = idx >> 8, k = idx & 255;
        unsigned short h, l;
        bf16_split(W2[(size_t)k * 256 + n], h, l);
        g_W2hi[idx] = __ushort_as_bfloat16(h);
        g_W2lo[idx] = __ushort_as_bfloat16(l);
    } else if (b < BX + BW1 + BW2 + BW3) {
        int idx = (b - BX - BW1 - BW2) * 256 + t;  // [N=64][K=256]
        int n = idx >> 8, k = idx & 255;
        unsigned short h, l;
        bf16_split(W3[(size_t)k * 64 + n], h, l);
        g_W3hi[idx] = __ushort_as_bfloat16(h);
        g_W3lo[idx] = __ushort_as_bfloat16(l);
    } else {
        int zi = (b - BX - BW1 - BW2 - BW3) * 256 + t;
        if (zi < NN) { g_cursor[zi] = 0; return; }
        zi -= NN;
        if (zi < GG * DD) { g_pool[zi] = 0.f; return; }
        zi -= GG * DD;
        if (zi < NN * 4) {
            g_als1[zi] = 0.f; g_ald1[zi] = 0.f;
            g_als2[zi] = 0.f; g_ald2[zi] = 0.f;
            return;
        }
        zi -= NN * 4;
        if (zi < NN) { g_als3[zi] = 0.f; g_ald3[zi] = 0.f; }
    }
}

// ---------------- CSR build ----------------
__global__ void count_k(const void* ei) {
    long long e = (long long)blockIdx.x * blockDim.x + threadIdx.x;
    if (e >= ETOT) return;
    int is64 = g_is64_ei;
    int d = (e < EE) ? ld_idx(ei, (long long)EE + e, is64) : (int)(e - EE);
    atomicAdd(&g_cursor[d], 1);
}

__global__ void scan_k() {
    __shared__ int wsum[32];
    const int CH = 49;
    int t = threadIdx.x;
    int base = t * CH;
    int s = 0;
    for (int i = 0; i < CH; i++) {
        int idx = base + i;
        if (idx < NN) s += g_cursor[idx];
    }
    int lane = t & 31, w = t >> 5;
    int v = s;
    #pragma unroll
    for (int o = 1; o < 32; o <<= 1) {
        int u = __shfl_up_sync(0xffffffffu, v, o);
        if (lane >= o) v += u;
    }
    if (lane == 31) wsum[w] = v;
    __syncthreads();
    if (w == 0) {
        int x = wsum[lane];
        #pragma unroll
        for (int o = 1; o < 32; o <<= 1) {
            int u = __shfl_up_sync(0xffffffffu, x, o);
            if (lane >= o) x += u;
        }
        wsum[lane] = x;
    }
    __syncthreads();
    int excl = v - s + (w > 0 ? wsum[w - 1] : 0);
    for (int i = 0; i < CH; i++) {
        int idx = base + i;
        if (idx < NN) {
            int c = g_cursor[idx];
            g_rowptr[idx] = excl;
            g_cursor[idx] = excl;
            excl += c;
        }
    }
    if (t == 1023) g_rowptr[NN] = excl;
}

__global__ void scatter_k(const void* ei) {
    long long e = (long long)blockIdx.x * blockDim.x + threadIdx.x;
    if (e >= ETOT) return;
    int is64 = g_is64_ei;
    int s, d;
    if (e < EE) {
        s = ld_idx(ei, e, is64);
        d = ld_idx(ei, (long long)EE + e, is64);
    } else {
        s = d = (int)(e - EE);
    }
    int pos = atomicAdd(&g_cursor[d], 1);
    g_esrc[pos] = s;
    g_eid[pos]  = (int)e;
}

// ---------------- bf16 3-split mma.sync GEMM + fused attention logits ----------------
template <int N_TILE, int THREADS, int HEADS>
__global__ void __launch_bounds__(THREADS) gemm_bf16_k(
    const __nv_bfloat16* __restrict__ Ahi, const __nv_bfloat16* __restrict__ Alo,
    const __nv_bfloat16* __restrict__ Bhi, const __nv_bfloat16* __restrict__ Blo,
    float* __restrict__ Cm,
    const float* __restrict__ a_src, const float* __restrict__ a_dst,
    float* __restrict__ alsO, float* __restrict__ aldO,
    int M, int K, int Nc) {
    constexpr int ABYTES = 128 * 64;
    constexpr int BBYTES = N_TILE * 64;
    constexpr int STAGE  = 2 * ABYTES + 2 * BBYTES;

    extern __shared__ char sm[];
    uint32_t sbase = smem_to_u32(sm);

    int tid = threadIdx.x;
    int warp = tid >> 5, lane = tid & 31;
    int rowBase = blockIdx.y * 128;
    int colBase = blockIdx.x * N_TILE;
    int wm = warp & 3;
    int wn = warp >> 2;

    float acc[2][4][4];
    #pragma unroll
    for (int i = 0; i < 2; i++)
        #pragma unroll
        for (int j = 0; j < 4; j++)
            #pragma unroll
            for (int q = 0; q < 4; q++) acc[i][j][q] = 0.f;

    auto load_chunk = [&](int c, int s) {
        int k0 = c * 32;
        uint32_t so = sbase + s * STAGE;
        #pragma unroll
        for (int u = tid; u < 512; u += THREADS) {
            int row = u >> 2, q = u & 3;
            uint32_t d = so + row * 64 + ((q ^ ((row >> 1) & 3)) * 16);
            size_t goff = (size_t)(rowBase + row) * K + k0 + q * 8;
            int sz = (rowBase + row < M) ? 16 : 0;
            cp_async16(d, Ahi + goff, sz);
            cp_async16(d + ABYTES, Alo + goff, sz);
        }
        #pragma unroll
        for (int u = tid; u < N_TILE * 4; u += THREADS) {
            int row = u >> 2, q = u & 3;
            uint32_t d = so + 2 * ABYTES + row * 64 + ((q ^ ((row >> 1) & 3)) * 16);
            size_t goff = (size_t)(colBase + row) * K + k0 + q * 8;
            cp_async16(d, Bhi + goff, 16);
            cp_async16(d + BBYTES, Blo + goff, 16);
        }
    };

    auto compute = [&](int s) {
        uint32_t aB = sbase + s * STAGE;
        uint32_t bB = aB + 2 * ABYTES;
        #pragma unroll
        for (int k16 = 0; k16 < 2; k16++) {
            int usel = k16 * 2 + (lane >> 4);
            uint32_t ahi[2][4], alo[2][4];
            #pragma unroll
            for (int mt = 0; mt < 2; mt++) {
                int row = wm * 32 + mt * 16 + (lane & 15);
                uint32_t addr = aB + row * 64 + ((usel ^ ((row >> 1) & 3)) * 16);
                ldsm_x4(ahi[mt], addr);
                ldsm_x4(alo[mt], addr + ABYTES);
            }
            uint32_t bhi[4][2], blo[4][2];
            #pragma unroll
            for (int half = 0; half < 2; half++) {
                int row = wn * 32 + half * 16 + (lane & 15);
                uint32_t addr = bB + row * 64 + ((usel ^ ((row >> 1) & 3)) * 16);
                uint32_t r[4], r2[4];
                ldsm_x4(r, addr);
                ldsm_x4(r2, addr + BBYTES);
                bhi[half * 2 + 0][0] = r[0];  bhi[half * 2 + 0][1] = r[2];
                bhi[half * 2 + 1][0] = r[1];  bhi[half * 2 + 1][1] = r[3];
                blo[half * 2 + 0][0] = r2[0]; blo[half * 2 + 0][1] = r2[2];
                blo[half * 2 + 1][0] = r2[1]; blo[half * 2 + 1][1] = r2[3];
            }
            #pragma unroll
            for (int mt = 0; mt < 2; mt++)
                #pragma unroll
                for (int nt = 0; nt < 4; nt++) {
                    mma_bf16(acc[mt][nt], ahi[mt], bhi[nt]);
                    mma_bf16(acc[mt][nt], ahi[mt], blo[nt]);
                    mma_bf16(acc[mt][nt], alo[mt], bhi[nt]);
                }
        }
    };

    int nch = K >> 5;
    load_chunk(0, 0);
    cp_commit();
    for (int c = 0; c < nch; c++) {
        if (c + 1 < nch) {
            load_chunk(c + 1, (c + 1) & 1);
            cp_commit();
            cp_wait<1>();
        } else {
            cp_wait<0>();
        }
        __syncthreads();
        compute(c & 1);
        __syncthreads();
    }

    // ---- epilogue: store C + fused attention logits ----
    int lq = lane & 3;
    int lr = lane >> 2;
    int head = (colBase + wn * 32) >> 6;
    #pragma unroll
    for (int mt = 0; mt < 2; mt++) {
        int r0 = rowBase + wm * 32 + mt * 16 + lr;
        float ss0 = 0.f, sd0 = 0.f, ss1 = 0.f, sd1 = 0.f;
        #pragma unroll
        for (int nt = 0; nt < 4; nt++) {
            int col = colBase + wn * 32 + nt * 8 + lq * 2;
            if (r0 < M)
                *(float2*)(Cm + (size_t)r0 * Nc + col) =
                    make_float2(acc[mt][nt][0], acc[mt][nt][1]);
            if (r0 + 8 < M)
                *(float2*)(Cm + (size_t)(r0 + 8) * Nc + col) =
                    make_float2(acc[mt][nt][2], acc[mt][nt][3]);
            float as0 = a_src[col], as1v = a_src[col + 1];
            float ad0 = a_dst[col], ad1v = a_dst[col + 1];
            ss0 += acc[mt][nt][0] * as0 + acc[mt][nt][1] * as1v;
            sd0 += acc[mt][nt][0] * ad0 + acc[mt][nt][1] * ad1v;
            ss1 += acc[mt][nt][2] * as0 + acc[mt][nt][3] * as1v;
            sd1 += acc[mt][nt][2] * ad0 + acc[mt][nt][3] * ad1v;
        }
        #pragma unroll
        for (int o = 1; o < 4; o <<= 1) {
            ss0 += __shfl_xor_sync(0xffffffffu, ss0, o);
            sd0 += __shfl_xor_sync(0xffffffffu, sd0, o);
            ss1 += __shfl_xor_sync(0xffffffffu, ss1, o);
            sd1 += __shfl_xor_sync(0xffffffffu, sd1, o);
        }
        if (lq == 0) {
            if (r0 < M) {
                atomicAdd(&alsO[r0 * HEADS + head], ss0);
                atomicAdd(&aldO[r0 * HEADS + head], sd0);
            }
            if (r0 + 8 < M) {
                atomicAdd(&alsO[(r0 + 8) * HEADS + head], ss1);
                atomicAdd(&aldO[(r0 + 8) * HEADS + head], sd1);
            }
        }
    }
}

// ---------------- GAT aggregation (warp per dst; no segment-max; shfl broadcast) ----
template <int HEADS>
__global__ void __launch_bounds__(256) aggregate_k(
    const float* __restrict__ hlin, const float* __restrict__ als,
    const float* __restrict__ ald, const float* __restrict__ bias,
    float* __restrict__ att, const void* batch) {
    int wid = (blockIdx.x * blockDim.x + threadIdx.x) >> 5;
    int lane = threadIdx.x & 31;
    if (wid >= NN) return;
    int n = wid;
    int st = g_rowptr[n], en = g_rowptr[n + 1];

    if (HEADS == 4) {
        float4 ad4 = ((const float4*)ald)[n];
        bool lo = lane < 16;
        float4 accA = make_float4(0.f, 0.f, 0.f, 0.f), accB = accA;
        float s0 = 0.f, s1 = 0.f, s2 = 0.f, s3 = 0.f;

        for (int base = st; base < en; base += 32) {
            int i = base + lane;
            int cnt = min(32, en - base);
            int s = 0;
            float ex0 = 0.f, ex1 = 0.f, ex2 = 0.f, ex3 = 0.f;
            if (i < en) {
                s = g_esrc[i];
                float4 av = ((const float4*)als)[s];
                ex0 = __expf(lrelu(av.x + ad4.x));
                ex1 = __expf(lrelu(av.y + ad4.y));
                ex2 = __expf(lrelu(av.z + ad4.z));
                ex3 = __expf(lrelu(av.w + ad4.w));
                s0 += ex0; s1 += ex1; s2 += ex2; s3 += ex3;
                __stcs(((float4*)g_scr) + i, make_float4(ex0, ex1, ex2, ex3));
            }
            for (int e = 0; e < cnt; e++) {
                int se = __shfl_sync(0xffffffffu, s, e);
                float e0 = __shfl_sync(0xffffffffu, ex0, e);
                float e1 = __shfl_sync(0xffffffffu, ex1, e);
                float e2 = __shfl_sync(0xffffffffu, ex2, e);
                float e3 = __shfl_sync(0xffffffffu, ex3, e);
                const float4* h4 = (const float4*)(hlin + (size_t)se * 256);
                float4 v0 = h4[lane], v1 = h4[32 + lane];
                float eA = lo ? e0 : e1;
                float eB = lo ? e2 : e3;
                accA.x += eA * v0.x; accA.y += eA * v0.y;
                accA.z += eA * v0.z; accA.w += eA * v0.w;
                accB.x += eB * v1.x; accB.y += eB * v1.y;
                accB.z += eB * v1.z; accB.w += eB * v1.w;
            }
        }
        #pragma unroll
        for (int o = 16; o; o >>= 1) {
            s0 += __shfl_xor_sync(0xffffffffu, s0, o);
            s1 += __shfl_xor_sync(0xffffffffu, s1, o);
            s2 += __shfl_xor_sync(0xffffffffu, s2, o);
            s3 += __shfl_xor_sync(0xffffffffu, s3, o);
        }
        float invA = 1.f / (lane < 16 ? s0 : s1);
        float invB = 1.f / (lane < 16 ? s2 : s3);
        const float4* b4 = (const float4*)bias;
        float4 bb0 = b4[lane], bb1 = b4[32 + lane];
        float4 o0, o1;
        o0.x = accA.x * invA + bb0.x; o0.y = accA.y * invA + bb0.y;
        o0.z = accA.z * invA + bb0.z; o0.w = accA.w * invA + bb0.w;
        o1.x = accB.x * invB + bb1.x; o1.y = accB.y * invB + bb1.y;
        o1.z = accB.z * invB + bb1.z; o1.w = accB.w * invB + bb1.w;
        o0.x = o0.x > 0.f ? o0.x : __expf(o0.x) - 1.f;
        o0.y = o0.y > 0.f ? o0.y : __expf(o0.y) - 1.f;
        o0.z = o0.z > 0.f ? o0.z : __expf(o0.z) - 1.f;
        o0.w = o0.w > 0.f ? o0.w : __expf(o0.w) - 1.f;
        o1.x = o1.x > 0.f ? o1.x : __expf(o1.x) - 1.f;
        o1.y = o1.y > 0.f ? o1.y : __expf(o1.y) - 1.f;
        o1.z = o1.z > 0.f ? o1.z : __expf(o1.z) - 1.f;
        o1.w = o1.w > 0.f ? o1.w : __expf(o1.w) - 1.f;
        unsigned short h0[4], l0[4], h1[4], l1[4];
        bf16_split(o0.x, h0[0], l0[0]); bf16_split(o0.y, h0[1], l0[1]);
        bf16_split(o0.z, h0[2], l0[2]); bf16_split(o0.w, h0[3], l0[3]);
        bf16_split(o1.x, h1[0], l1[0]); bf16_split(o1.y, h1[1], l1[1]);
        bf16_split(o1.z, h1[2], l1[2]); bf16_split(o1.w, h1[3], l1[3]);
        *(uint2*)(g_Ahi + (size_t)n * 256 + lane * 4) =
            make_uint2((uint32_t)h0[0] | ((uint32_t)h0[1] << 16),
                       (uint32_t)h0[2] | ((uint32_t)h0[3] << 16));
        *(uint2*)(g_Alo + (size_t)n * 256 + lane * 4) =
            make_uint2((uint32_t)l0[0] | ((uint32_t)l0[1] << 16),
                       (uint32_t)l0[2] | ((uint32_t)l0[3] << 16));
        *(uint2*)(g_Ahi + (size_t)n * 256 + 128 + lane * 4) =
            make_uint2((uint32_t)h1[0] | ((uint32_t)h1[1] << 16),
                       (uint32_t)h1[2] | ((uint32_t)h1[3] << 16));
        *(uint2*)(g_Alo + (size_t)n * 256 + 128 + lane * 4) =
            make_uint2((uint32_t)l1[0] | ((uint32_t)l1[1] << 16),
                       (uint32_t)l1[2] | ((uint32_t)l1[3] << 16));
        float4 inv4 = make_float4(1.f / s0, 1.f / s1, 1.f / s2, 1.f / s3);
        for (int i = st + lane; i < en; i += 32) {
            float4 exv = __ldcs(((const float4*)g_scr) + i);
            int id = g_eid[i];
            __stcs(((float4*)att) + id,
                   make_float4(exv.x * inv4.x, exv.y * inv4.y,
                               exv.z * inv4.z, exv.w * inv4.w));
        }
    } else {
        float ad = ald[n];
        float2 acc = make_float2(0.f, 0.f);
        float ssum = 0.f;
        for (int base = st; base < en; base += 32) {
            int i = base + lane;
            int cnt = min(32, en - base);
            int s = 0;
            float ex = 0.f;
            if (i < en) {
                s = g_esrc[i];
                ex = __expf(lrelu(als[s] + ad));
                ssum += ex;
                __stcs(&g_scr[i], ex);
            }
            for (int e = 0; e < cnt; e++) {
                int se = __shfl_sync(0xffffffffu, s, e);
                float e0 = __shfl_sync(0xffffffffu, ex, e);
                float2 v = ((const float2*)(hlin + (size_t)se * 64))[lane];
                acc.x += e0 * v.x;
                acc.y += e0 * v.y;
            }
        }
        #pragma unroll
        for (int o = 16; o; o >>= 1)
            ssum += __shfl_xor_sync(0xffffffffu, ssum, o);
        float inv = 1.f / ssum;
        float2 bb = ((const float2*)bias)[lane];
        float2 o;
        o.x = acc.x * inv + bb.x;
        o.y = acc.y * inv + bb.y;
        int g = ld_idx(batch, n, g_is64_b);
        atomicAdd(&g_pool[g * DD + lane * 2 + 0], o.x);
        atomicAdd(&g_pool[g * DD + lane * 2 + 1], o.y);
        for (int i = st + lane; i < en; i += 32) {
            float exv = __ldcs(&g_scr[i]);
            int id = g_eid[i];
            __stcs(&att[id], exv * inv);
        }
    }
}

// ---------------- classifier ----------------
__global__ void classifier_k(const float* __restrict__ Wc1, const float* __restrict__ bc1,
                             const float* __restrict__ Wc2, const float* __restrict__ bc2,
                             float* __restrict__ out, const void* batch) {
    __shared__ int bnd[GG + 1];
    __shared__ float hid[GG][33];
    int t = threadIdx.x;
    if (t <= GG) {
        int lo = 0, hi = NN;
        while (lo < hi) {
            int mid = (lo + hi) >> 1;
            if (ld_idx(batch, mid, g_is64_b) < t) lo = mid + 1;
            else hi = mid;
        }
        bnd[t] = lo;
    }
    __syncthreads();
    for (int idx = t; idx < GG * 32; idx += blockDim.x) {
        int g = idx >> 5, j = idx & 31;
        float cnt = (float)(bnd[g + 1] - bnd[g]);
        float inv = 1.f / fmaxf(cnt, 1.f);
        float s = bc1[j];
        #pragma unroll
        for (int d = 0; d < DD; d++)
            s += (g_pool[g * DD + d] * inv) * Wc1[d * 32 + j];
        hid[g][j] = fmaxf(s, 0.f);
    }
    __syncthreads();
    for (int idx = t; idx < GG * CC; idx += blockDim.x) {
        int g = idx / CC, c = idx % CC;
        float s = bc2[c];
        #pragma unroll
        for (int j = 0; j < 32; j++)
            s += hid[g][j] * Wc2[j * CC + c];
        out[g * CC + c] = s;
    }
}

// ---------------- launch ----------------
extern "C" void kernel_launch(void* const* d_in, const int* in_sizes, int n_in,
                              void* d_out, int out_size) {
    const float* x   = (const float*)d_in[0];
    const void*  ei  = d_in[1];
    const void*  bat = d_in[2];
    const float* W1  = (const float*)d_in[3];
    const float* as1 = (const float*)d_in[4];
    const float* ad1 = (const float*)d_in[5];
    const float* b1  = (const float*)d_in[6];
    const float* W2  = (const float*)d_in[7];
    const float* as2 = (const float*)d_in[8];
    const float* ad2 = (const float*)d_in[9];
    const float* b2  = (const float*)d_in[10];
    const float* W3  = (const float*)d_in[11];
    const float* as3 = (const float*)d_in[12];
    const float* ad3 = (const float*)d_in[13];
    const float* b3  = (const float*)d_in[14];
    const float* Wc1 = (const float*)d_in[15];
    const float* bc1 = (const float*)d_in[16];
    const float* Wc2 = (const float*)d_in[17];
    const float* bc2 = (const float*)d_in[18];

    float* out  = (float*)d_out;
    float* att1 = out + GG * CC;
    float* att2 = att1 + (size_t)ETOT * 4;
    float* att3 = att2 + (size_t)ETOT * 4;

    float* bufA;
    cudaGetSymbolAddress((void**)&bufA, g_bufA);
    __nv_bfloat16 *Ahi, *Alo, *W1h, *W1l, *W2h, *W2l, *W3h, *W3l;
    cudaGetSymbolAddress((void**)&Ahi, g_Ahi);
    cudaGetSymbolAddress((void**)&Alo, g_Alo);
    cudaGetSymbolAddress((void**)&W1h, g_W1hi);
    cudaGetSymbolAddress((void**)&W1l, g_W1lo);
    cudaGetSymbolAddress((void**)&W2h, g_W2hi);
    cudaGetSymbolAddress((void**)&W2l, g_W2lo);
    cudaGetSymbolAddress((void**)&W3h, g_W3hi);
    cudaGetSymbolAddress((void**)&W3l, g_W3lo);
    float *als1, *ald1, *als2, *ald2, *als3, *ald3;
    cudaGetSymbolAddress((void**)&als1, g_als1);
    cudaGetSymbolAddress((void**)&ald1, g_ald1);
    cudaGetSymbolAddress((void**)&als2, g_als2);
    cudaGetSymbolAddress((void**)&ald2, g_ald2);
    cudaGetSymbolAddress((void**)&als3, g_als3);
    cudaGetSymbolAddress((void**)&ald3, g_ald3);

    const int NB_E = (ETOT + 255) / 256;
    const int NB_W = (NN * 32 + 255) / 256;
    const int MB   = (NN + 127) / 128;

    const int SMEM128 = 2 * (2 * 128 * 64 + 2 * 128 * 64);  // 65536
    const int SMEM64  = 2 * (2 * 128 * 64 + 2 * 64 * 64);   // 49152
    cudaFuncSetAttribute((const void*)gemm_bf16_k<128, 512, 4>,
                         cudaFuncAttributeMaxDynamicSharedMemorySize, SMEM128);
    cudaFuncSetAttribute((const void*)gemm_bf16_k<64, 256, 1>,
                         cudaFuncAttributeMaxDynamicSharedMemorySize, SMEM64);

    // NOTE: gemm1 placed as the 4th launch so ncu profiles it.
    prep_k<<<PREP_BLOCKS, 256>>>(x, W1, W2, W3, ei, bat);
    count_k<<<NB_E, 256>>>(ei);
    scan_k<<<1, 1024>>>();

    // Layer 1 GEMM (depends only on prep)
    gemm_bf16_k<128, 512, 4><<<dim3(2, MB), 512, SMEM128>>>(
        Ahi, Alo, W1h, W1l, bufA, as1, ad1, als1, ald1, NN, FF, 256);

    scatter_k<<<NB_E, 256>>>(ei);   // CSR finalize (before any aggregate)

    aggregate_k<4><<<NB_W, 256>>>(bufA, als1, ald1, b1, att1, bat);

    // Layer 2
    gemm_bf16_k<128, 512, 4><<<dim3(2, MB), 512, SMEM128>>>(
        Ahi, Alo, W2h, W2l, bufA, as2, ad2, als2, ald2, NN, 256, 256);
    aggregate_k<4><<<NB_W, 256>>>(bufA, als2, ald2, b2, att2, bat);

    // Layer 3
    gemm_bf16_k<64, 256, 1><<<dim3(1, MB), 256, SMEM64>>>(
        Ahi, Alo, W3h, W3l, bufA, as3, ad3, als3, ald3, NN, 256, 64);
    aggregate_k<1><<<NB_W, 256>>>(bufA, als3, ald3, b3, att3, bat);

    classifier_k<<<1, 256>>>(Wc1, bc1, Wc2, bc2, out, bat);
}